// round 1
// baseline (speedup 1.0000x reference)
#include <cuda_runtime.h>
#include <math.h>

// Problem dims
#define B_  2
#define T_  2048
#define S_  2048
#define D_  1024
#define H_  16
#define DK_ 64

// Scratch (device globals; no allocation allowed)
__device__ float g_q[B_*H_*T_*DK_];     // [b][h][t][dk], pre-scaled by 1/sqrt(DK)
__device__ float g_k[B_*H_*S_*DK_];     // [b][h][s][dk]
__device__ float g_v[B_*H_*S_*DK_];     // [b][h][s][dk]
__device__ float g_attn[B_*T_*H_*DK_];  // [b][t][h][dk] == [m][1024] row-major

// ---------------------------------------------------------------------------
// SGEMM: C[M=4096, N=1024] = A[4096,1024] @ W[1024,1024] (+bias)*scale
// MODE 0/1/2: write q/k/v in [b][h][t][dk] layout.  MODE 3: A=g_attn, plain C.
// 128x128 tile, BK=8, 256 threads, 8x8 per thread.
// ---------------------------------------------------------------------------
template<int MODE>
__global__ __launch_bounds__(256) void sgemm_kernel(
    const float* __restrict__ Ain, const float* __restrict__ W,
    const float* __restrict__ bias, float* __restrict__ Cout, float scale)
{
    __shared__ float As[8][128];
    __shared__ float Bs[8][128];

    const float* A = (MODE == 3) ? (const float*)g_attn : Ain;

    const int tid = threadIdx.x;
    const int m0 = blockIdx.y * 128;
    const int n0 = blockIdx.x * 128;
    const int a_row = tid >> 1;           // 0..127
    const int a_col = (tid & 1) << 2;     // 0 or 4
    const int b_row = tid >> 5;           // 0..7
    const int b_col = (tid & 31) << 2;    // 0..124
    const int ty = tid >> 4;              // 0..15
    const int tx = tid & 15;              // 0..15

    float acc[8][8];
    #pragma unroll
    for (int i = 0; i < 8; i++)
        #pragma unroll
        for (int j = 0; j < 8; j++) acc[i][j] = 0.f;

    for (int k0 = 0; k0 < 1024; k0 += 8) {
        float4 av = *(const float4*)&A[(size_t)(m0 + a_row) * 1024 + k0 + a_col];
        float4 bv = *(const float4*)&W[(size_t)(k0 + b_row) * 1024 + n0 + b_col];
        __syncthreads();
        As[a_col + 0][a_row] = av.x;
        As[a_col + 1][a_row] = av.y;
        As[a_col + 2][a_row] = av.z;
        As[a_col + 3][a_row] = av.w;
        *(float4*)&Bs[b_row][b_col] = bv;
        __syncthreads();
        #pragma unroll
        for (int kk = 0; kk < 8; kk++) {
            float ra[8], rb[8];
            *(float4*)&ra[0] = *(const float4*)&As[kk][ty * 4];
            *(float4*)&ra[4] = *(const float4*)&As[kk][64 + ty * 4];
            *(float4*)&rb[0] = *(const float4*)&Bs[kk][tx * 4];
            *(float4*)&rb[4] = *(const float4*)&Bs[kk][64 + tx * 4];
            #pragma unroll
            for (int i = 0; i < 8; i++)
                #pragma unroll
                for (int j = 0; j < 8; j++)
                    acc[i][j] = fmaf(ra[i], rb[j], acc[i][j]);
        }
    }

    float* Cq = (MODE == 0) ? g_q : (MODE == 1) ? g_k : (MODE == 2) ? g_v : Cout;

    #pragma unroll
    for (int i = 0; i < 8; i++) {
        int m = m0 + ((i < 4) ? (ty * 4 + i) : (64 + ty * 4 + (i - 4)));
        #pragma unroll
        for (int j = 0; j < 8; j++) {
            int n = n0 + ((j < 4) ? (tx * 4 + j) : (64 + tx * 4 + (j - 4)));
            float val = (acc[i][j] + bias[n]) * scale;
            if (MODE < 3) {
                int b = m >> 11, t = m & 2047;
                int h = n >> 6,  dk = n & 63;
                Cq[(((size_t)(b * H_ + h)) * T_ + t) * DK_ + dk] = val;
            } else {
                Cq[(size_t)m * 1024 + n] = val;
            }
        }
    }
}

// ---------------------------------------------------------------------------
// Flash attention, fp32. One block = 64 query rows of one (b,h).
// BR=64, BC=32, DK=64. 256 threads: ty=tid/8 in [0,32) owns 2 rows,
// tx=tid&7 owns 4 score cols / 8 O cols.
// Smem: Qts [dk][row] 64x68, KP = K as [dk][s] 64x36 (reused for P^T [s][row]),
//       Vs [s][dk] 32x68.  Total 35328 B (static).
// ---------------------------------------------------------------------------
__global__ __launch_bounds__(256) void flash_kernel()
{
    __shared__ float Qts[64 * 68];
    __shared__ float KP [64 * 36];
    __shared__ float Vs [32 * 68];

    const int tid = threadIdx.x;
    const int bh  = blockIdx.y;          // b*H + h
    const int t0  = blockIdx.x * 64;
    const int ty  = tid >> 3;            // 0..31
    const int tx  = tid & 7;             // 0..7
    const float L2E = 1.4426950408889634f;

    // Load Q tile transposed: Qts[dk][row]
    const float* qb = g_q + (size_t)bh * T_ * DK_ + (size_t)t0 * DK_;
    for (int p = tid; p < 64 * 16; p += 256) {
        int row = p >> 4;
        int d4  = (p & 15) << 2;
        float4 x = *(const float4*)&qb[row * 64 + d4];
        Qts[(d4 + 0) * 68 + row] = x.x;
        Qts[(d4 + 1) * 68 + row] = x.y;
        Qts[(d4 + 2) * 68 + row] = x.z;
        Qts[(d4 + 3) * 68 + row] = x.w;
    }

    float m_[2] = {-1e30f, -1e30f};
    float l_[2] = {0.f, 0.f};
    float O[2][8];
    #pragma unroll
    for (int i = 0; i < 2; i++)
        #pragma unroll
        for (int j = 0; j < 8; j++) O[i][j] = 0.f;

    for (int s0 = 0; s0 < S_; s0 += 32) {
        __syncthreads();   // previous tile's P/V reads complete
        const float* kb = g_k + (size_t)bh * S_ * DK_ + (size_t)s0 * DK_;
        const float* vb = g_v + (size_t)bh * S_ * DK_ + (size_t)s0 * DK_;
        for (int p = tid; p < 32 * 16; p += 256) {
            int c  = p >> 4;
            int d4 = (p & 15) << 2;
            float4 x = *(const float4*)&kb[c * 64 + d4];
            KP[(d4 + 0) * 36 + c] = x.x;
            KP[(d4 + 1) * 36 + c] = x.y;
            KP[(d4 + 2) * 36 + c] = x.z;
            KP[(d4 + 3) * 36 + c] = x.w;
            *(float4*)&Vs[c * 68 + d4] = *(const float4*)&vb[c * 64 + d4];
        }
        __syncthreads();

        // scores: S4[i][j] = sum_dk Q[r][dk] * K[c][dk]   (q already /sqrt(dk))
        float S4[2][4];
        #pragma unroll
        for (int i = 0; i < 2; i++)
            #pragma unroll
            for (int j = 0; j < 4; j++) S4[i][j] = 0.f;
        #pragma unroll 8
        for (int kk = 0; kk < 64; kk++) {
            float2 a  = *(const float2*)&Qts[kk * 68 + ty * 2];
            float4 b4 = *(const float4*)&KP [kk * 36 + tx * 4];
            S4[0][0] = fmaf(a.x, b4.x, S4[0][0]);
            S4[0][1] = fmaf(a.x, b4.y, S4[0][1]);
            S4[0][2] = fmaf(a.x, b4.z, S4[0][2]);
            S4[0][3] = fmaf(a.x, b4.w, S4[0][3]);
            S4[1][0] = fmaf(a.y, b4.x, S4[1][0]);
            S4[1][1] = fmaf(a.y, b4.y, S4[1][1]);
            S4[1][2] = fmaf(a.y, b4.z, S4[1][2]);
            S4[1][3] = fmaf(a.y, b4.w, S4[1][3]);
        }

        // online softmax (exp2 domain)
        float p_[2][4];
        #pragma unroll
        for (int i = 0; i < 2; i++) {
            #pragma unroll
            for (int j = 0; j < 4; j++) S4[i][j] *= L2E;
            float tm = S4[i][0];
            #pragma unroll
            for (int j = 1; j < 4; j++) tm = fmaxf(tm, S4[i][j]);
            #pragma unroll
            for (int off = 1; off < 8; off <<= 1)
                tm = fmaxf(tm, __shfl_xor_sync(0xffffffffu, tm, off, 8));
            float mn   = fmaxf(m_[i], tm);
            float corr = exp2f(m_[i] - mn);
            m_[i] = mn;
            float rs = 0.f;
            #pragma unroll
            for (int j = 0; j < 4; j++) {
                p_[i][j] = exp2f(S4[i][j] - mn);
                rs += p_[i][j];
            }
            #pragma unroll
            for (int off = 1; off < 8; off <<= 1)
                rs += __shfl_xor_sync(0xffffffffu, rs, off, 8);
            l_[i] = l_[i] * corr + rs;
            #pragma unroll
            for (int j = 0; j < 8; j++) O[i][j] *= corr;
        }

        __syncthreads();   // all score reads of KP done before overwriting with P^T
        #pragma unroll
        for (int i = 0; i < 2; i++)
            #pragma unroll
            for (int j = 0; j < 4; j++)
                KP[(tx * 4 + j) * 68 + ty * 2 + i] = p_[i][j];
        __syncthreads();

        // O += P^T' @ V   (accumulate over the 32 tile columns)
        #pragma unroll 8
        for (int c = 0; c < 32; c++) {
            float2 pa = *(const float2*)&KP[c * 68 + ty * 2];
            float4 v0 = *(const float4*)&Vs[c * 68 + tx * 8];
            float4 v1 = *(const float4*)&Vs[c * 68 + tx * 8 + 4];
            O[0][0] = fmaf(pa.x, v0.x, O[0][0]);
            O[0][1] = fmaf(pa.x, v0.y, O[0][1]);
            O[0][2] = fmaf(pa.x, v0.z, O[0][2]);
            O[0][3] = fmaf(pa.x, v0.w, O[0][3]);
            O[0][4] = fmaf(pa.x, v1.x, O[0][4]);
            O[0][5] = fmaf(pa.x, v1.y, O[0][5]);
            O[0][6] = fmaf(pa.x, v1.z, O[0][6]);
            O[0][7] = fmaf(pa.x, v1.w, O[0][7]);
            O[1][0] = fmaf(pa.y, v0.x, O[1][0]);
            O[1][1] = fmaf(pa.y, v0.y, O[1][1]);
            O[1][2] = fmaf(pa.y, v0.z, O[1][2]);
            O[1][3] = fmaf(pa.y, v0.w, O[1][3]);
            O[1][4] = fmaf(pa.y, v1.x, O[1][4]);
            O[1][5] = fmaf(pa.y, v1.y, O[1][5]);
            O[1][6] = fmaf(pa.y, v1.z, O[1][6]);
            O[1][7] = fmaf(pa.y, v1.w, O[1][7]);
        }
    }

    // epilogue: normalize and write attn as [b][t][h][dk]
    const int b = bh >> 4, h = bh & 15;
    #pragma unroll
    for (int i = 0; i < 2; i++) {
        float inv = 1.f / l_[i];
        int t = t0 + ty * 2 + i;
        float* ob = g_attn + (((size_t)(b * T_ + t)) * H_ + h) * DK_ + tx * 8;
        float4 o0, o1;
        o0.x = O[i][0] * inv; o0.y = O[i][1] * inv;
        o0.z = O[i][2] * inv; o0.w = O[i][3] * inv;
        o1.x = O[i][4] * inv; o1.y = O[i][5] * inv;
        o1.z = O[i][6] * inv; o1.w = O[i][7] * inv;
        *(float4*)&ob[0] = o0;
        *(float4*)&ob[4] = o1;
    }
}

// ---------------------------------------------------------------------------
extern "C" void kernel_launch(void* const* d_in, const int* in_sizes, int n_in,
                              void* d_out, int out_size)
{
    (void)in_sizes; (void)n_in; (void)out_size;
    const float* query = (const float*)d_in[0];
    const float* value = (const float*)d_in[1];
    const float* key   = (const float*)d_in[2];
    const float* Wq    = (const float*)d_in[3];
    const float* bq    = (const float*)d_in[4];
    const float* Wk    = (const float*)d_in[5];
    const float* bk    = (const float*)d_in[6];
    const float* Wv    = (const float*)d_in[7];
    const float* bv    = (const float*)d_in[8];
    const float* Wo    = (const float*)d_in[9];
    const float* bo    = (const float*)d_in[10];
    float* out = (float*)d_out;

    dim3 gg(8, 32), gb(256);
    const float qscale = 0.125f;  // 1/sqrt(64)

    sgemm_kernel<0><<<gg, gb>>>(query, Wq, bq, nullptr, qscale);
    sgemm_kernel<1><<<gg, gb>>>(key,   Wk, bk, nullptr, 1.f);
    sgemm_kernel<2><<<gg, gb>>>(value, Wv, bv, nullptr, 1.f);
    flash_kernel<<<dim3(T_ / 64, B_ * H_), 256>>>();
    sgemm_kernel<3><<<gg, gb>>>(nullptr, Wo, bo, out, 1.f);
}

// round 6
// speedup vs baseline: 1.2009x; 1.2009x over previous
#include <cuda_runtime.h>
#include <cuda_bf16.h>
#include <cstdint>
#include <math.h>

// Problem dims
#define B_  2
#define T_  2048
#define S_  2048
#define D_  1024
#define H_  16
#define DK_ 64

// ---------------------------------------------------------------------------
// Scratch (device globals; no allocation allowed)
// ---------------------------------------------------------------------------
__device__ float g_q[B_*H_*T_*DK_];     // [b][h][t][dk], pre-scaled by 1/sqrt(DK)
__device__ float g_k[B_*H_*S_*DK_];     // [b][h][s][dk]
__device__ float g_v[B_*H_*S_*DK_];     // [b][h][s][dk]
__device__ float g_attn[B_*T_*H_*DK_];  // [b][t][h][dk] == [m][1024] row-major

__device__ __nv_bfloat16 g_a_hi[4096*1024];   // GEMM A split, [m][k]
__device__ __nv_bfloat16 g_a_lo[4096*1024];
__device__ __nv_bfloat16 g_bt_hi[1024*1024];  // W^T split, [n][k]
__device__ __nv_bfloat16 g_bt_lo[1024*1024];

// ---------------------------------------------------------------------------
// Helpers (base-sm_103-safe: mma.sync / ldmatrix / cp.async only)
// ---------------------------------------------------------------------------
__device__ __forceinline__ uint32_t smem_to_u32(const void* p) {
    uint32_t a;
    asm("{ .reg .u64 t; cvta.to.shared.u64 t, %1; cvt.u32.u64 %0, t; }" : "=r"(a) : "l"(p));
    return a;
}
__device__ __forceinline__ void cp16(uint32_t d, const void* s) {
    asm volatile("cp.async.cg.shared.global [%0], [%1], 16;" :: "r"(d), "l"(s));
}
__device__ __forceinline__ void cp_commit() { asm volatile("cp.async.commit_group;" ::: "memory"); }
template<int N> __device__ __forceinline__ void cp_wait() {
    asm volatile("cp.async.wait_group %0;" :: "n"(N) : "memory");
}
__device__ __forceinline__ void ldsm4(uint32_t* r, uint32_t a) {
    asm volatile("ldmatrix.sync.aligned.m8n8.x4.shared.b16 {%0,%1,%2,%3}, [%4];"
                 : "=r"(r[0]), "=r"(r[1]), "=r"(r[2]), "=r"(r[3]) : "r"(a));
}
__device__ __forceinline__ void mma_bf16(float* c, const uint32_t* a, uint32_t b0, uint32_t b1) {
    asm volatile(
        "mma.sync.aligned.m16n8k16.row.col.f32.bf16.bf16.f32 "
        "{%0,%1,%2,%3}, {%4,%5,%6,%7}, {%8,%9}, {%0,%1,%2,%3};"
        : "+f"(c[0]), "+f"(c[1]), "+f"(c[2]), "+f"(c[3])
        : "r"(a[0]), "r"(a[1]), "r"(a[2]), "r"(a[3]), "r"(b0), "r"(b1));
}
// 128B-row smem, 16B-column XOR swizzle (conflict-free for ldmatrix)
__device__ __forceinline__ uint32_t swz(uint32_t base, int row, int c16) {
    return base + (uint32_t)row * 128u + (((uint32_t)(c16 ^ (row & 7))) << 4);
}
__device__ __forceinline__ uint32_t pbf2(float x, float y) {
    __nv_bfloat162 t = __floats2bfloat162_rn(x, y);
    return *reinterpret_cast<uint32_t*>(&t);
}
__device__ __forceinline__ void split2(float x, float y, uint32_t& hi, uint32_t& lo) {
    __nv_bfloat16 hx = __float2bfloat16(x), hy = __float2bfloat16(y);
    hi = pbf2(__bfloat162float(hx), __bfloat162float(hy));  // exact repack
    lo = pbf2(x - __bfloat162float(hx), y - __bfloat162float(hy));
}

// ---------------------------------------------------------------------------
// Split conversion kernels
// ---------------------------------------------------------------------------
__global__ __launch_bounds__(256) void asplit_kernel(const float* __restrict__ x)
{
    const float* src = x ? x : (const float*)g_attn;
    int i = blockIdx.x * 256 + threadIdx.x;   // float4 index, 0..1048575
    float4 v = ((const float4*)src)[i];
    uint32_t h0, l0, h1, l1;
    split2(v.x, v.y, h0, l0);
    split2(v.z, v.w, h1, l1);
    uint32_t* ph = (uint32_t*)g_a_hi;
    uint32_t* pl = (uint32_t*)g_a_lo;
    ph[2*i] = h0; ph[2*i+1] = h1;
    pl[2*i] = l0; pl[2*i+1] = l1;
}

__global__ __launch_bounds__(256) void wsplit_kernel(const float* __restrict__ W)
{
    __shared__ float tile[32][33];
    const int n0 = blockIdx.x * 32, d0 = blockIdx.y * 32;
    const int tx = threadIdx.x & 31, ty = threadIdx.x >> 5;
    #pragma unroll
    for (int r = ty; r < 32; r += 8)
        tile[r][tx] = W[(size_t)(d0 + r) * 1024 + n0 + tx];
    __syncthreads();
    #pragma unroll
    for (int r = ty; r < 32; r += 8) {
        float v = tile[tx][r];   // = W[d0+tx][n0+r]
        __nv_bfloat16 h = __float2bfloat16(v);
        size_t o = (size_t)(n0 + r) * 1024 + d0 + tx;
        g_bt_hi[o] = h;
        g_bt_lo[o] = __float2bfloat16(v - __bfloat162float(h));
    }
}

// ---------------------------------------------------------------------------
// GEMM: C[4096,1024] = A @ W (+bias)*scale, mma.sync bf16 split (3 products).
// BM=128 BN=64 BK=32. STATIC smem only: 2 stages x 24KB = 48KB exactly.
// Per stage: A 128 rows x 128B (hi k32 at c16 0-3, lo at 4-7) @0,
//            B  64 rows x 128B (same interleave)              @16384.
// MODE 0/1/2: fp32 scatter to g_q/g_k/g_v [b][h][t][dk]; MODE 3: plain Cout.
// ---------------------------------------------------------------------------
template<int MODE>
__global__ __launch_bounds__(256) void gemm_mma_kernel(
    const float* __restrict__ bias, float* __restrict__ Cout, float scale)
{
    __shared__ uint8_t sm[49152];
    const uint32_t sb0 = smem_to_u32(sm);
    const int tid = threadIdx.x;
    const int lane = tid & 31, w = tid >> 5;
    const int wm = w >> 1, wn = w & 1;           // 4 x 2 warp grid (32m x 32n each)
    const int n0 = blockIdx.x * 64, m0 = blockIdx.y * 128;
    const int rlo = lane & 15, chf = lane >> 4;

    float acc[2][4][4];
    #pragma unroll
    for (int a = 0; a < 2; a++)
        #pragma unroll
        for (int b = 0; b < 4; b++)
            #pragma unroll
            for (int c = 0; c < 4; c++) acc[a][b][c] = 0.f;

    auto load_stage = [&](int st, int k0) {
        const uint32_t sbase = sb0 + (uint32_t)st * 24576u;
        #pragma unroll
        for (int it = 0; it < 6; it++) {
            int idx = it * 256 + tid;            // 0..1535
            if (idx < 1024) {                    // A: 128 rows x 8 slots
                int row = idx >> 3, c16 = idx & 7;
                const __nv_bfloat16* src = (c16 < 4) ? g_a_hi : g_a_lo;
                cp16(swz(sbase, row, c16),
                     src + (size_t)(m0 + row) * 1024 + k0 + (c16 & 3) * 8);
            } else {                             // B: 64 rows x 8 slots
                int j = idx - 1024;
                int row = j >> 3, c16 = j & 7;
                const __nv_bfloat16* src = (c16 < 4) ? g_bt_hi : g_bt_lo;
                cp16(swz(sbase + 16384u, row, c16),
                     src + (size_t)(n0 + row) * 1024 + k0 + (c16 & 3) * 8);
            }
        }
    };

    load_stage(0, 0);
    cp_commit();

    for (int itk = 0; itk < 32; itk++) {
        __syncthreads();
        if (itk + 1 < 32) { load_stage((itk + 1) & 1, (itk + 1) * 32); cp_commit(); }
        if (itk + 1 < 32) cp_wait<1>(); else cp_wait<0>();
        __syncthreads();

        const uint32_t Ab = sb0 + (uint32_t)(itk & 1) * 24576u;
        const uint32_t Bb = Ab + 16384u;
        #pragma unroll
        for (int ks = 0; ks < 2; ks++) {
            uint32_t ah[2][4], al[2][4];
            #pragma unroll
            for (int mf = 0; mf < 2; mf++) {
                const int arow = wm * 32 + mf * 16 + rlo;
                ldsm4(ah[mf], swz(Ab, arow, ks * 2 + chf));
                ldsm4(al[mf], swz(Ab, arow, ks * 2 + chf + 4));
            }
            #pragma unroll
            for (int h2 = 0; h2 < 2; h2++) {
                uint32_t bh[4], bl[4];
                const int brow = wn * 32 + h2 * 16 + rlo;
                ldsm4(bh, swz(Bb, brow, ks * 2 + chf));
                ldsm4(bl, swz(Bb, brow, ks * 2 + chf + 4));
                #pragma unroll
                for (int i = 0; i < 2; i++) {
                    const int nf = h2 * 2 + i;
                    #pragma unroll
                    for (int mf = 0; mf < 2; mf++) {
                        mma_bf16(acc[mf][nf], ah[mf], bh[i], bh[i + 2]);
                        mma_bf16(acc[mf][nf], ah[mf], bl[i], bl[i + 2]);
                        mma_bf16(acc[mf][nf], al[mf], bh[i], bh[i + 2]);
                    }
                }
            }
        }
    }

    // Epilogue
    const int g = lane >> 2, t4 = lane & 3;
    #pragma unroll
    for (int mf = 0; mf < 2; mf++) {
        #pragma unroll
        for (int nf = 0; nf < 4; nf++) {
            const int m = m0 + wm * 32 + mf * 16 + g;
            const int n = n0 + wn * 32 + nf * 8 + t4 * 2;
            const float b0 = __ldg(&bias[n]), b1 = __ldg(&bias[n + 1]);
            const float v00 = (acc[mf][nf][0] + b0) * scale;
            const float v01 = (acc[mf][nf][1] + b1) * scale;
            const float v10 = (acc[mf][nf][2] + b0) * scale;
            const float v11 = (acc[mf][nf][3] + b1) * scale;
            if (MODE == 3) {
                *(float2*)&Cout[(size_t)m * 1024 + n]       = make_float2(v00, v01);
                *(float2*)&Cout[(size_t)(m + 8) * 1024 + n] = make_float2(v10, v11);
            } else {
                float* tgt = (MODE == 0) ? g_q : (MODE == 1) ? g_k : g_v;
                const int bb = m >> 11, tq = m & 2047;
                const int hh = n >> 6, dk = n & 63;
                const size_t o0 = (((size_t)(bb * 16 + hh)) * 2048 + tq) * 64 + dk;
                *(float2*)&tgt[o0]           = make_float2(v00, v01);
                *(float2*)&tgt[o0 + 8 * 64]  = make_float2(v10, v11);
            }
        }
    }
}

// ---------------------------------------------------------------------------
// Flash attention, fp32 — VERBATIM round-1 proven-correct kernel.
// ---------------------------------------------------------------------------
__global__ __launch_bounds__(256) void flash_kernel()
{
    __shared__ float Qts[64 * 68];
    __shared__ float KP [64 * 36];
    __shared__ float Vs [32 * 68];

    const int tid = threadIdx.x;
    const int bh  = blockIdx.y;
    const int t0  = blockIdx.x * 64;
    const int ty  = tid >> 3;
    const int tx  = tid & 7;
    const float L2E = 1.4426950408889634f;

    const float* qb = g_q + (size_t)bh * T_ * DK_ + (size_t)t0 * DK_;
    for (int p = tid; p < 64 * 16; p += 256) {
        int row = p >> 4;
        int d4  = (p & 15) << 2;
        float4 x = *(const float4*)&qb[row * 64 + d4];
        Qts[(d4 + 0) * 68 + row] = x.x;
        Qts[(d4 + 1) * 68 + row] = x.y;
        Qts[(d4 + 2) * 68 + row] = x.z;
        Qts[(d4 + 3) * 68 + row] = x.w;
    }

    float m_[2] = {-1e30f, -1e30f};
    float l_[2] = {0.f, 0.f};
    float O[2][8];
    #pragma unroll
    for (int i = 0; i < 2; i++)
        #pragma unroll
        for (int j = 0; j < 8; j++) O[i][j] = 0.f;

    for (int s0 = 0; s0 < S_; s0 += 32) {
        __syncthreads();
        const float* kb = g_k + (size_t)bh * S_ * DK_ + (size_t)s0 * DK_;
        const float* vb = g_v + (size_t)bh * S_ * DK_ + (size_t)s0 * DK_;
        for (int p = tid; p < 32 * 16; p += 256) {
            int c  = p >> 4;
            int d4 = (p & 15) << 2;
            float4 x = *(const float4*)&kb[c * 64 + d4];
            KP[(d4 + 0) * 36 + c] = x.x;
            KP[(d4 + 1) * 36 + c] = x.y;
            KP[(d4 + 2) * 36 + c] = x.z;
            KP[(d4 + 3) * 36 + c] = x.w;
            *(float4*)&Vs[c * 68 + d4] = *(const float4*)&vb[c * 64 + d4];
        }
        __syncthreads();

        float S4[2][4];
        #pragma unroll
        for (int i = 0; i < 2; i++)
            #pragma unroll
            for (int j = 0; j < 4; j++) S4[i][j] = 0.f;
        #pragma unroll 8
        for (int kk = 0; kk < 64; kk++) {
            float2 a  = *(const float2*)&Qts[kk * 68 + ty * 2];
            float4 b4 = *(const float4*)&KP [kk * 36 + tx * 4];
            S4[0][0] = fmaf(a.x, b4.x, S4[0][0]);
            S4[0][1] = fmaf(a.x, b4.y, S4[0][1]);
            S4[0][2] = fmaf(a.x, b4.z, S4[0][2]);
            S4[0][3] = fmaf(a.x, b4.w, S4[0][3]);
            S4[1][0] = fmaf(a.y, b4.x, S4[1][0]);
            S4[1][1] = fmaf(a.y, b4.y, S4[1][1]);
            S4[1][2] = fmaf(a.y, b4.z, S4[1][2]);
            S4[1][3] = fmaf(a.y, b4.w, S4[1][3]);
        }

        float p_[2][4];
        #pragma unroll
        for (int i = 0; i < 2; i++) {
            #pragma unroll
            for (int j = 0; j < 4; j++) S4[i][j] *= L2E;
            float tm = S4[i][0];
            #pragma unroll
            for (int j = 1; j < 4; j++) tm = fmaxf(tm, S4[i][j]);
            #pragma unroll
            for (int off = 1; off < 8; off <<= 1)
                tm = fmaxf(tm, __shfl_xor_sync(0xffffffffu, tm, off, 8));
            float mn   = fmaxf(m_[i], tm);
            float corr = exp2f(m_[i] - mn);
            m_[i] = mn;
            float rs = 0.f;
            #pragma unroll
            for (int j = 0; j < 4; j++) {
                p_[i][j] = exp2f(S4[i][j] - mn);
                rs += p_[i][j];
            }
            #pragma unroll
            for (int off = 1; off < 8; off <<= 1)
                rs += __shfl_xor_sync(0xffffffffu, rs, off, 8);
            l_[i] = l_[i] * corr + rs;
            #pragma unroll
            for (int j = 0; j < 8; j++) O[i][j] *= corr;
        }

        __syncthreads();
        #pragma unroll
        for (int i = 0; i < 2; i++)
            #pragma unroll
            for (int j = 0; j < 4; j++)
                KP[(tx * 4 + j) * 68 + ty * 2 + i] = p_[i][j];
        __syncthreads();

        #pragma unroll 8
        for (int c = 0; c < 32; c++) {
            float2 pa = *(const float2*)&KP[c * 68 + ty * 2];
            float4 v0 = *(const float4*)&Vs[c * 68 + tx * 8];
            float4 v1 = *(const float4*)&Vs[c * 68 + tx * 8 + 4];
            O[0][0] = fmaf(pa.x, v0.x, O[0][0]);
            O[0][1] = fmaf(pa.x, v0.y, O[0][1]);
            O[0][2] = fmaf(pa.x, v0.z, O[0][2]);
            O[0][3] = fmaf(pa.x, v0.w, O[0][3]);
            O[0][4] = fmaf(pa.x, v1.x, O[0][4]);
            O[0][5] = fmaf(pa.x, v1.y, O[0][5]);
            O[0][6] = fmaf(pa.x, v1.z, O[0][6]);
            O[0][7] = fmaf(pa.x, v1.w, O[0][7]);
            O[1][0] = fmaf(pa.y, v0.x, O[1][0]);
            O[1][1] = fmaf(pa.y, v0.y, O[1][1]);
            O[1][2] = fmaf(pa.y, v0.z, O[1][2]);
            O[1][3] = fmaf(pa.y, v0.w, O[1][3]);
            O[1][4] = fmaf(pa.y, v1.x, O[1][4]);
            O[1][5] = fmaf(pa.y, v1.y, O[1][5]);
            O[1][6] = fmaf(pa.y, v1.z, O[1][6]);
            O[1][7] = fmaf(pa.y, v1.w, O[1][7]);
        }
    }

    const int b = bh >> 4, h = bh & 15;
    #pragma unroll
    for (int i = 0; i < 2; i++) {
        float inv = 1.f / l_[i];
        int t = t0 + ty * 2 + i;
        float* ob = g_attn + (((size_t)(b * T_ + t)) * H_ + h) * DK_ + tx * 8;
        float4 o0, o1;
        o0.x = O[i][0] * inv; o0.y = O[i][1] * inv;
        o0.z = O[i][2] * inv; o0.w = O[i][3] * inv;
        o1.x = O[i][4] * inv; o1.y = O[i][5] * inv;
        o1.z = O[i][6] * inv; o1.w = O[i][7] * inv;
        *(float4*)&ob[0] = o0;
        *(float4*)&ob[4] = o1;
    }
}

// ---------------------------------------------------------------------------
extern "C" void kernel_launch(void* const* d_in, const int* in_sizes, int n_in,
                              void* d_out, int out_size)
{
    (void)in_sizes; (void)n_in; (void)out_size;
    const float* query = (const float*)d_in[0];
    const float* value = (const float*)d_in[1];
    const float* key   = (const float*)d_in[2];
    const float* Wq    = (const float*)d_in[3];
    const float* bq    = (const float*)d_in[4];
    const float* Wk    = (const float*)d_in[5];
    const float* bk    = (const float*)d_in[6];
    const float* Wv    = (const float*)d_in[7];
    const float* bv    = (const float*)d_in[8];
    const float* Wo    = (const float*)d_in[9];
    const float* bo    = (const float*)d_in[10];
    float* out = (float*)d_out;

    const dim3 ggrid(16, 32);         // 1024/64 x 4096/128
    const float qscale = 0.125f;      // 1/sqrt(64)

    asplit_kernel<<<4096, 256>>>(query);
    wsplit_kernel<<<dim3(32, 32), 256>>>(Wq);
    gemm_mma_kernel<0><<<ggrid, 256>>>(bq, nullptr, qscale);

    asplit_kernel<<<4096, 256>>>(key);
    wsplit_kernel<<<dim3(32, 32), 256>>>(Wk);
    gemm_mma_kernel<1><<<ggrid, 256>>>(bk, nullptr, 1.f);

    asplit_kernel<<<4096, 256>>>(value);
    wsplit_kernel<<<dim3(32, 32), 256>>>(Wv);
    gemm_mma_kernel<2><<<ggrid, 256>>>(bv, nullptr, 1.f);

    flash_kernel<<<dim3(T_ / 64, B_ * H_), 256>>>();

    asplit_kernel<<<4096, 256>>>(nullptr);       // split g_attn
    wsplit_kernel<<<dim3(32, 32), 256>>>(Wo);
    gemm_mma_kernel<3><<<ggrid, 256>>>(bo, out, 1.f);
}

// round 7
// speedup vs baseline: 3.4538x; 2.8759x over previous
#include <cuda_runtime.h>
#include <cuda_bf16.h>
#include <cstdint>
#include <math.h>

// Problem dims
#define B_  2
#define T_  2048
#define S_  2048
#define D_  1024
#define H_  16
#define DK_ 64

// ---------------------------------------------------------------------------
// Scratch (device globals; no allocation allowed)
// ---------------------------------------------------------------------------
__device__ float g_attn[B_*T_*H_*DK_];        // [b][t][h][dk] == [m][1024]

__device__ __nv_bfloat16 g_qh[B_*H_*T_*DK_];  // q/k/v split hi/lo, [b][h][t][dk]
__device__ __nv_bfloat16 g_ql[B_*H_*T_*DK_];
__device__ __nv_bfloat16 g_kh[B_*H_*S_*DK_];
__device__ __nv_bfloat16 g_kl[B_*H_*S_*DK_];
__device__ __nv_bfloat16 g_vh[B_*H_*S_*DK_];
__device__ __nv_bfloat16 g_vl[B_*H_*S_*DK_];

__device__ __nv_bfloat16 g_a_hi[4096*1024];   // GEMM A split, [m][k]
__device__ __nv_bfloat16 g_a_lo[4096*1024];
__device__ __nv_bfloat16 g_bt_hi[1024*1024];  // W^T split, [n][k]
__device__ __nv_bfloat16 g_bt_lo[1024*1024];

// ---------------------------------------------------------------------------
// Helpers (base-sm_103-safe: mma.sync / ldmatrix / cp.async only)
// ---------------------------------------------------------------------------
__device__ __forceinline__ uint32_t smem_to_u32(const void* p) {
    uint32_t a;
    asm("{ .reg .u64 t; cvta.to.shared.u64 t, %1; cvt.u32.u64 %0, t; }" : "=r"(a) : "l"(p));
    return a;
}
__device__ __forceinline__ void cp16(uint32_t d, const void* s) {
    asm volatile("cp.async.cg.shared.global [%0], [%1], 16;" :: "r"(d), "l"(s));
}
__device__ __forceinline__ void cp_commit() { asm volatile("cp.async.commit_group;" ::: "memory"); }
template<int N> __device__ __forceinline__ void cp_wait() {
    asm volatile("cp.async.wait_group %0;" :: "n"(N) : "memory");
}
__device__ __forceinline__ void ldsm4(uint32_t* r, uint32_t a) {
    asm volatile("ldmatrix.sync.aligned.m8n8.x4.shared.b16 {%0,%1,%2,%3}, [%4];"
                 : "=r"(r[0]), "=r"(r[1]), "=r"(r[2]), "=r"(r[3]) : "r"(a));
}
__device__ __forceinline__ void ldsm4t(uint32_t* r, uint32_t a) {
    asm volatile("ldmatrix.sync.aligned.m8n8.x4.trans.shared.b16 {%0,%1,%2,%3}, [%4];"
                 : "=r"(r[0]), "=r"(r[1]), "=r"(r[2]), "=r"(r[3]) : "r"(a));
}
__device__ __forceinline__ void mma_bf16(float* c, const uint32_t* a, uint32_t b0, uint32_t b1) {
    asm volatile(
        "mma.sync.aligned.m16n8k16.row.col.f32.bf16.bf16.f32 "
        "{%0,%1,%2,%3}, {%4,%5,%6,%7}, {%8,%9}, {%0,%1,%2,%3};"
        : "+f"(c[0]), "+f"(c[1]), "+f"(c[2]), "+f"(c[3])
        : "r"(a[0]), "r"(a[1]), "r"(a[2]), "r"(a[3]), "r"(b0), "r"(b1));
}
__device__ __forceinline__ float ex2(float x) {
    float y;
    asm("ex2.approx.f32 %0, %1;" : "=f"(y) : "f"(x));
    return y;
}
// 128B-row smem, 16B-column XOR swizzle (conflict-free for ldmatrix)
__device__ __forceinline__ uint32_t swz(uint32_t base, int row, int c16) {
    return base + (uint32_t)row * 128u + (((uint32_t)(c16 ^ (row & 7))) << 4);
}
__device__ __forceinline__ uint32_t pbf2(float x, float y) {
    __nv_bfloat162 t = __floats2bfloat162_rn(x, y);
    return *reinterpret_cast<uint32_t*>(&t);
}
__device__ __forceinline__ void split2(float x, float y, uint32_t& hi, uint32_t& lo) {
    __nv_bfloat16 hx = __float2bfloat16(x), hy = __float2bfloat16(y);
    hi = pbf2(__bfloat162float(hx), __bfloat162float(hy));  // exact repack
    lo = pbf2(x - __bfloat162float(hx), y - __bfloat162float(hy));
}

// ---------------------------------------------------------------------------
// Split conversion kernels
// ---------------------------------------------------------------------------
__global__ __launch_bounds__(256) void asplit_kernel(const float* __restrict__ x)
{
    const float* src = x ? x : (const float*)g_attn;
    int i = blockIdx.x * 256 + threadIdx.x;   // float4 index
    float4 v = ((const float4*)src)[i];
    uint32_t h0, l0, h1, l1;
    split2(v.x, v.y, h0, l0);
    split2(v.z, v.w, h1, l1);
    uint32_t* ph = (uint32_t*)g_a_hi;
    uint32_t* pl = (uint32_t*)g_a_lo;
    ph[2*i] = h0; ph[2*i+1] = h1;
    pl[2*i] = l0; pl[2*i+1] = l1;
}

__global__ __launch_bounds__(256) void wsplit_kernel(const float* __restrict__ W)
{
    __shared__ float tile[32][33];
    const int n0 = blockIdx.x * 32, d0 = blockIdx.y * 32;
    const int tx = threadIdx.x & 31, ty = threadIdx.x >> 5;
    #pragma unroll
    for (int r = ty; r < 32; r += 8)
        tile[r][tx] = W[(size_t)(d0 + r) * 1024 + n0 + tx];
    __syncthreads();
    #pragma unroll
    for (int r = ty; r < 32; r += 8) {
        float v = tile[tx][r];   // = W[d0+tx][n0+r]
        __nv_bfloat16 h = __float2bfloat16(v);
        size_t o = (size_t)(n0 + r) * 1024 + d0 + tx;
        g_bt_hi[o] = h;
        g_bt_lo[o] = __float2bfloat16(v - __bfloat162float(h));
    }
}

// ---------------------------------------------------------------------------
// GEMM: C[4096,1024] = A @ W (+bias)*scale, mma.sync bf16 split (3 products).
// BM=128 BN=64 BK=32, static 48KB smem (validated round 6).
// MODE 0/1/2: split-bf16 scatter to g_{q,k,v}{h,l} [b][h][t][dk]; MODE 3: fp32 Cout.
// ---------------------------------------------------------------------------
template<int MODE>
__global__ __launch_bounds__(256) void gemm_mma_kernel(
    const float* __restrict__ bias, float* __restrict__ Cout, float scale)
{
    __shared__ uint8_t sm[49152];
    const uint32_t sb0 = smem_to_u32(sm);
    const int tid = threadIdx.x;
    const int lane = tid & 31, w = tid >> 5;
    const int wm = w >> 1, wn = w & 1;           // 4 x 2 warp grid (32m x 32n each)
    const int n0 = blockIdx.x * 64, m0 = blockIdx.y * 128;
    const int rlo = lane & 15, chf = lane >> 4;

    float acc[2][4][4];
    #pragma unroll
    for (int a = 0; a < 2; a++)
        #pragma unroll
        for (int b = 0; b < 4; b++)
            #pragma unroll
            for (int c = 0; c < 4; c++) acc[a][b][c] = 0.f;

    auto load_stage = [&](int st, int k0) {
        const uint32_t sbase = sb0 + (uint32_t)st * 24576u;
        #pragma unroll
        for (int it = 0; it < 6; it++) {
            int idx = it * 256 + tid;            // 0..1535
            if (idx < 1024) {                    // A: 128 rows x 8 slots
                int row = idx >> 3, c16 = idx & 7;
                const __nv_bfloat16* src = (c16 < 4) ? g_a_hi : g_a_lo;
                cp16(swz(sbase, row, c16),
                     src + (size_t)(m0 + row) * 1024 + k0 + (c16 & 3) * 8);
            } else {                             // B: 64 rows x 8 slots
                int j = idx - 1024;
                int row = j >> 3, c16 = j & 7;
                const __nv_bfloat16* src = (c16 < 4) ? g_bt_hi : g_bt_lo;
                cp16(swz(sbase + 16384u, row, c16),
                     src + (size_t)(n0 + row) * 1024 + k0 + (c16 & 3) * 8);
            }
        }
    };

    load_stage(0, 0);
    cp_commit();

    for (int itk = 0; itk < 32; itk++) {
        __syncthreads();
        if (itk + 1 < 32) { load_stage((itk + 1) & 1, (itk + 1) * 32); cp_commit(); }
        if (itk + 1 < 32) cp_wait<1>(); else cp_wait<0>();
        __syncthreads();

        const uint32_t Ab = sb0 + (uint32_t)(itk & 1) * 24576u;
        const uint32_t Bb = Ab + 16384u;
        #pragma unroll
        for (int ks = 0; ks < 2; ks++) {
            uint32_t ah[2][4], al[2][4];
            #pragma unroll
            for (int mf = 0; mf < 2; mf++) {
                const int arow = wm * 32 + mf * 16 + rlo;
                ldsm4(ah[mf], swz(Ab, arow, ks * 2 + chf));
                ldsm4(al[mf], swz(Ab, arow, ks * 2 + chf + 4));
            }
            #pragma unroll
            for (int h2 = 0; h2 < 2; h2++) {
                uint32_t bh[4], bl[4];
                const int brow = wn * 32 + h2 * 16 + rlo;
                ldsm4(bh, swz(Bb, brow, ks * 2 + chf));
                ldsm4(bl, swz(Bb, brow, ks * 2 + chf + 4));
                #pragma unroll
                for (int i = 0; i < 2; i++) {
                    const int nf = h2 * 2 + i;
                    #pragma unroll
                    for (int mf = 0; mf < 2; mf++) {
                        mma_bf16(acc[mf][nf], ah[mf], bh[i], bh[i + 2]);
                        mma_bf16(acc[mf][nf], ah[mf], bl[i], bl[i + 2]);
                        mma_bf16(acc[mf][nf], al[mf], bh[i], bh[i + 2]);
                    }
                }
            }
        }
    }

    // Epilogue
    const int g = lane >> 2, t4 = lane & 3;
    #pragma unroll
    for (int mf = 0; mf < 2; mf++) {
        #pragma unroll
        for (int nf = 0; nf < 4; nf++) {
            const int m = m0 + wm * 32 + mf * 16 + g;
            const int n = n0 + wn * 32 + nf * 8 + t4 * 2;
            const float b0 = __ldg(&bias[n]), b1 = __ldg(&bias[n + 1]);
            const float v00 = (acc[mf][nf][0] + b0) * scale;
            const float v01 = (acc[mf][nf][1] + b1) * scale;
            const float v10 = (acc[mf][nf][2] + b0) * scale;
            const float v11 = (acc[mf][nf][3] + b1) * scale;
            if (MODE == 3) {
                *(float2*)&Cout[(size_t)m * 1024 + n]       = make_float2(v00, v01);
                *(float2*)&Cout[(size_t)(m + 8) * 1024 + n] = make_float2(v10, v11);
            } else {
                __nv_bfloat16* th = (MODE == 0) ? g_qh : (MODE == 1) ? g_kh : g_vh;
                __nv_bfloat16* tl = (MODE == 0) ? g_ql : (MODE == 1) ? g_kl : g_vl;
                const int bb = m >> 11, tq = m & 2047;
                const int hh = n >> 6, dk = n & 63;
                const size_t o0 = (((size_t)(bb * 16 + hh)) * 2048 + tq) * 64 + dk;
                uint32_t hv, lv;
                split2(v00, v01, hv, lv);
                *(uint32_t*)&th[o0] = hv; *(uint32_t*)&tl[o0] = lv;
                split2(v10, v11, hv, lv);
                *(uint32_t*)&th[o0 + 8 * 64] = hv; *(uint32_t*)&tl[o0 + 8 * 64] = lv;
            }
        }
    }
}

// ---------------------------------------------------------------------------
// Flash attention via mma.sync bf16 split. BR=128/CTA, BC=32, DK=64.
// 8 warps; warp w owns rows [w*16, w*16+16). Q frags persist in registers.
// STATIC smem 48KB: prologue Q hi@0 lo@16K (128x128B each); then the same
// region becomes 2 KV stages of 16KB: Kh@0, Kl@4K, Vh@8K, Vl@12K (32x128B).
// ---------------------------------------------------------------------------
__global__ __launch_bounds__(256) void flash_mma_kernel()
{
    __shared__ uint8_t sm[49152];
    const uint32_t sb0 = smem_to_u32(sm);
    const int tid = threadIdx.x, lane = tid & 31, w = tid >> 5;
    const int bh = blockIdx.y, t0 = blockIdx.x * 128;
    const size_t qoff = (size_t)bh * (2048 * 64) + (size_t)t0 * 64;
    const size_t kvb = (size_t)bh * (2048 * 64);
    const int rlo = lane & 15, chf = lane >> 4;
    const float L2E = 1.4426950408889634f;

    // ---- Prologue: Q hi/lo to smem, then to register fragments ----
    #pragma unroll
    for (int it = 0; it < 8; it++) {
        int idx = it * 256 + tid;           // 0..2047
        int buf = idx >> 10;                // 0 hi, 1 lo
        int row = (idx & 1023) >> 3, c16 = idx & 7;
        const __nv_bfloat16* src = buf ? g_ql : g_qh;
        cp16(swz(sb0 + (uint32_t)buf * 16384u, row, c16),
             src + qoff + (size_t)row * 64 + c16 * 8);
    }
    cp_commit();
    cp_wait<0>();
    __syncthreads();

    uint32_t qh[4][4], ql[4][4];
    #pragma unroll
    for (int ks = 0; ks < 4; ks++) {
        ldsm4(qh[ks], swz(sb0,           w * 16 + rlo, ks * 2 + chf));
        ldsm4(ql[ks], swz(sb0 + 16384u,  w * 16 + rlo, ks * 2 + chf));
    }
    __syncthreads();   // Q reads done before KV overwrites smem

    auto load_kv = [&](int st, int s0) {
        const uint32_t sbase = sb0 + (uint32_t)st * 16384u;
        #pragma unroll
        for (int it = 0; it < 4; it++) {
            int idx = it * 256 + tid;       // 0..1023
            int buf = idx >> 8;             // 0 Kh, 1 Kl, 2 Vh, 3 Vl
            int row = (idx & 255) >> 3, c16 = idx & 7;
            const __nv_bfloat16* src = (buf == 0) ? g_kh : (buf == 1) ? g_kl
                                     : (buf == 2) ? g_vh : g_vl;
            cp16(swz(sbase + (uint32_t)buf * 4096u, row, c16),
                 src + kvb + (size_t)(s0 + row) * 64 + c16 * 8);
        }
    };

    load_kv(0, 0);
    cp_commit();

    float O[8][4];
    #pragma unroll
    for (int a = 0; a < 8; a++)
        #pragma unroll
        for (int b = 0; b < 4; b++) O[a][b] = 0.f;
    float m0_ = -1e30f, m1_ = -1e30f, l0_ = 0.f, l1_ = 0.f;

    for (int i = 0; i < 64; i++) {
        __syncthreads();
        if (i + 1 < 64) { load_kv((i + 1) & 1, (i + 1) * 32); cp_commit(); }
        if (i + 1 < 64) cp_wait<1>(); else cp_wait<0>();
        __syncthreads();

        const uint32_t Kb = sb0 + (uint32_t)(i & 1) * 16384u;
        const uint32_t Vb = Kb + 8192u;

        // ---- scores: S[16 x 32] per warp ----
        float sacc[4][4];
        #pragma unroll
        for (int a = 0; a < 4; a++)
            #pragma unroll
            for (int b = 0; b < 4; b++) sacc[a][b] = 0.f;

        #pragma unroll
        for (int ks = 0; ks < 4; ks++) {
            #pragma unroll
            for (int h2 = 0; h2 < 2; h2++) {
                uint32_t kb[4], lb[4];
                ldsm4(kb, swz(Kb,          h2 * 16 + rlo, ks * 2 + chf));
                ldsm4(lb, swz(Kb + 4096u,  h2 * 16 + rlo, ks * 2 + chf));
                #pragma unroll
                for (int ii = 0; ii < 2; ii++) {
                    const int nf = h2 * 2 + ii;
                    mma_bf16(sacc[nf], qh[ks], kb[ii], kb[ii + 2]);
                    mma_bf16(sacc[nf], qh[ks], lb[ii], lb[ii + 2]);
                    mma_bf16(sacc[nf], ql[ks], kb[ii], kb[ii + 2]);
                }
            }
        }

        // ---- online softmax (rows g, g+8 per thread) ----
        float tm0 = -1e30f, tm1 = -1e30f;
        #pragma unroll
        for (int nf = 0; nf < 4; nf++) {
            tm0 = fmaxf(tm0, fmaxf(sacc[nf][0], sacc[nf][1]));
            tm1 = fmaxf(tm1, fmaxf(sacc[nf][2], sacc[nf][3]));
        }
        tm0 = fmaxf(tm0, __shfl_xor_sync(0xffffffffu, tm0, 1));
        tm0 = fmaxf(tm0, __shfl_xor_sync(0xffffffffu, tm0, 2));
        tm1 = fmaxf(tm1, __shfl_xor_sync(0xffffffffu, tm1, 1));
        tm1 = fmaxf(tm1, __shfl_xor_sync(0xffffffffu, tm1, 2));
        float mn0 = fmaxf(m0_, tm0), mn1 = fmaxf(m1_, tm1);
        float c0 = ex2((m0_ - mn0) * L2E), c1 = ex2((m1_ - mn1) * L2E);
        m0_ = mn0; m1_ = mn1;

        uint32_t ph0[4], ph1[4], pl0[4], pl1[4];
        float s0 = 0.f, s1 = 0.f;
        #pragma unroll
        for (int nf = 0; nf < 4; nf++) {
            float p00 = ex2((sacc[nf][0] - mn0) * L2E);
            float p01 = ex2((sacc[nf][1] - mn0) * L2E);
            float p10 = ex2((sacc[nf][2] - mn1) * L2E);
            float p11 = ex2((sacc[nf][3] - mn1) * L2E);
            s0 += p00 + p01; s1 += p10 + p11;
            split2(p00, p01, ph0[nf], pl0[nf]);
            split2(p10, p11, ph1[nf], pl1[nf]);
        }
        s0 += __shfl_xor_sync(0xffffffffu, s0, 1);
        s0 += __shfl_xor_sync(0xffffffffu, s0, 2);
        s1 += __shfl_xor_sync(0xffffffffu, s1, 1);
        s1 += __shfl_xor_sync(0xffffffffu, s1, 2);
        l0_ = l0_ * c0 + s0;
        l1_ = l1_ * c1 + s1;
        #pragma unroll
        for (int nd = 0; nd < 8; nd++) {
            O[nd][0] *= c0; O[nd][1] *= c0;
            O[nd][2] *= c1; O[nd][3] *= c1;
        }

        // ---- O += P @ V ----
        #pragma unroll
        for (int ks2 = 0; ks2 < 2; ks2++) {
            uint32_t ah[4] = { ph0[2 * ks2], ph1[2 * ks2], ph0[2 * ks2 + 1], ph1[2 * ks2 + 1] };
            uint32_t al[4] = { pl0[2 * ks2], pl1[2 * ks2], pl0[2 * ks2 + 1], pl1[2 * ks2 + 1] };
            #pragma unroll
            for (int h2 = 0; h2 < 4; h2++) {
                uint32_t vb[4], wb[4];
                ldsm4t(vb, swz(Vb,          ks2 * 16 + rlo, h2 * 2 + chf));
                ldsm4t(wb, swz(Vb + 4096u,  ks2 * 16 + rlo, h2 * 2 + chf));
                #pragma unroll
                for (int ii = 0; ii < 2; ii++) {
                    const int nd = h2 * 2 + ii;
                    mma_bf16(O[nd], ah, vb[2 * ii], vb[2 * ii + 1]);
                    mma_bf16(O[nd], ah, wb[2 * ii], wb[2 * ii + 1]);
                    mma_bf16(O[nd], al, vb[2 * ii], vb[2 * ii + 1]);
                }
            }
        }
    }

    // ---- epilogue: normalize, write [b][t][h][dk] fp32 ----
    const int g = lane >> 2, t4 = lane & 3;
    const int bb = bh >> 4, hh = bh & 15;
    const float inv0 = 1.f / l0_, inv1 = 1.f / l1_;
    const int tq = t0 + w * 16 + g;
    #pragma unroll
    for (int nd = 0; nd < 8; nd++) {
        const int col = nd * 8 + t4 * 2;
        *(float2*)&g_attn[(((size_t)(bb * 2048 + tq)) * 16 + hh) * 64 + col] =
            make_float2(O[nd][0] * inv0, O[nd][1] * inv0);
        *(float2*)&g_attn[(((size_t)(bb * 2048 + tq + 8)) * 16 + hh) * 64 + col] =
            make_float2(O[nd][2] * inv1, O[nd][3] * inv1);
    }
}

// ---------------------------------------------------------------------------
extern "C" void kernel_launch(void* const* d_in, const int* in_sizes, int n_in,
                              void* d_out, int out_size)
{
    (void)in_sizes; (void)n_in; (void)out_size;
    const float* query = (const float*)d_in[0];
    const float* value = (const float*)d_in[1];
    const float* key   = (const float*)d_in[2];
    const float* Wq    = (const float*)d_in[3];
    const float* bq    = (const float*)d_in[4];
    const float* Wk    = (const float*)d_in[5];
    const float* bk    = (const float*)d_in[6];
    const float* Wv    = (const float*)d_in[7];
    const float* bv    = (const float*)d_in[8];
    const float* Wo    = (const float*)d_in[9];
    const float* bo    = (const float*)d_in[10];
    float* out = (float*)d_out;

    const dim3 ggrid(16, 32);         // 1024/64 x 4096/128
    const float qscale = 0.125f;      // 1/sqrt(64)

    asplit_kernel<<<4096, 256>>>(query);
    wsplit_kernel<<<dim3(32, 32), 256>>>(Wq);
    gemm_mma_kernel<0><<<ggrid, 256>>>(bq, nullptr, qscale);

    asplit_kernel<<<4096, 256>>>(key);
    wsplit_kernel<<<dim3(32, 32), 256>>>(Wk);
    gemm_mma_kernel<1><<<ggrid, 256>>>(bk, nullptr, 1.f);

    asplit_kernel<<<4096, 256>>>(value);
    wsplit_kernel<<<dim3(32, 32), 256>>>(Wv);
    gemm_mma_kernel<2><<<ggrid, 256>>>(bv, nullptr, 1.f);

    flash_mma_kernel<<<dim3(T_ / 128, B_ * H_), 256>>>();

    asplit_kernel<<<4096, 256>>>(nullptr);       // split g_attn
    wsplit_kernel<<<dim3(32, 32), 256>>>(Wo);
    gemm_mma_kernel<3><<<ggrid, 256>>>(bo, out, 1.f);
}

// round 9
// speedup vs baseline: 3.6551x; 1.0583x over previous
#include <cuda_runtime.h>
#include <cuda_bf16.h>
#include <cstdint>
#include <math.h>

// Problem dims
#define B_  2
#define T_  2048
#define S_  2048
#define D_  1024
#define H_  16
#define DK_ 64

// ---------------------------------------------------------------------------
// Scratch (device globals; no allocation allowed)
// ---------------------------------------------------------------------------
// GEMM A operands, split hi/lo, [m][k] row-major (m=4096, k=1024)
__device__ __nv_bfloat16 g_aq_hi[4096*1024];
__device__ __nv_bfloat16 g_aq_lo[4096*1024];
__device__ __nv_bfloat16 g_ak_hi[4096*1024];
__device__ __nv_bfloat16 g_ak_lo[4096*1024];
__device__ __nv_bfloat16 g_av_hi[4096*1024];
__device__ __nv_bfloat16 g_av_lo[4096*1024];
__device__ __nv_bfloat16 g_ao_hi[4096*1024];   // attn output (written by flash)
__device__ __nv_bfloat16 g_ao_lo[4096*1024];
// W^T operands, split, [n][k]
__device__ __nv_bfloat16 g_wq_hi[1024*1024];
__device__ __nv_bfloat16 g_wq_lo[1024*1024];
__device__ __nv_bfloat16 g_wk_hi[1024*1024];
__device__ __nv_bfloat16 g_wk_lo[1024*1024];
__device__ __nv_bfloat16 g_wv_hi[1024*1024];
__device__ __nv_bfloat16 g_wv_lo[1024*1024];
__device__ __nv_bfloat16 g_wo_hi[1024*1024];
__device__ __nv_bfloat16 g_wo_lo[1024*1024];
// Projected q/k/v, split hi/lo, [b][h][t][dk]
__device__ __nv_bfloat16 g_qh[B_*H_*T_*DK_];
__device__ __nv_bfloat16 g_ql[B_*H_*T_*DK_];
__device__ __nv_bfloat16 g_kh[B_*H_*S_*DK_];
__device__ __nv_bfloat16 g_kl[B_*H_*S_*DK_];
__device__ __nv_bfloat16 g_vh[B_*H_*S_*DK_];
__device__ __nv_bfloat16 g_vl[B_*H_*S_*DK_];

// ---------------------------------------------------------------------------
// Helpers (base-sm_103-safe: mma.sync / ldmatrix / cp.async only)
// ---------------------------------------------------------------------------
__device__ __forceinline__ uint32_t smem_to_u32(const void* p) {
    uint32_t a;
    asm("{ .reg .u64 t; cvta.to.shared.u64 t, %1; cvt.u32.u64 %0, t; }" : "=r"(a) : "l"(p));
    return a;
}
__device__ __forceinline__ void cp16(uint32_t d, const void* s) {
    asm volatile("cp.async.cg.shared.global [%0], [%1], 16;" :: "r"(d), "l"(s));
}
__device__ __forceinline__ void cp_commit() { asm volatile("cp.async.commit_group;" ::: "memory"); }
template<int N> __device__ __forceinline__ void cp_wait() {
    asm volatile("cp.async.wait_group %0;" :: "n"(N) : "memory");
}
__device__ __forceinline__ void ldsm4(uint32_t* r, uint32_t a) {
    asm volatile("ldmatrix.sync.aligned.m8n8.x4.shared.b16 {%0,%1,%2,%3}, [%4];"
                 : "=r"(r[0]), "=r"(r[1]), "=r"(r[2]), "=r"(r[3]) : "r"(a));
}
__device__ __forceinline__ void ldsm4t(uint32_t* r, uint32_t a) {
    asm volatile("ldmatrix.sync.aligned.m8n8.x4.trans.shared.b16 {%0,%1,%2,%3}, [%4];"
                 : "=r"(r[0]), "=r"(r[1]), "=r"(r[2]), "=r"(r[3]) : "r"(a));
}
__device__ __forceinline__ void mma_bf16(float* c, const uint32_t* a, uint32_t b0, uint32_t b1) {
    asm volatile(
        "mma.sync.aligned.m16n8k16.row.col.f32.bf16.bf16.f32 "
        "{%0,%1,%2,%3}, {%4,%5,%6,%7}, {%8,%9}, {%0,%1,%2,%3};"
        : "+f"(c[0]), "+f"(c[1]), "+f"(c[2]), "+f"(c[3])
        : "r"(a[0]), "r"(a[1]), "r"(a[2]), "r"(a[3]), "r"(b0), "r"(b1));
}
__device__ __forceinline__ float ex2(float x) {
    float y;
    asm("ex2.approx.f32 %0, %1;" : "=f"(y) : "f"(x));
    return y;
}
// 128B-row smem, 16B-column XOR swizzle (conflict-free for ldmatrix)
__device__ __forceinline__ uint32_t swz(uint32_t base, int row, int c16) {
    return base + (uint32_t)row * 128u + (((uint32_t)(c16 ^ (row & 7))) << 4);
}
__device__ __forceinline__ uint32_t pbf2(float x, float y) {
    __nv_bfloat162 t = __floats2bfloat162_rn(x, y);
    return *reinterpret_cast<uint32_t*>(&t);
}
__device__ __forceinline__ void split2(float x, float y, uint32_t& hi, uint32_t& lo) {
    __nv_bfloat16 hx = __float2bfloat16(x), hy = __float2bfloat16(y);
    hi = pbf2(__bfloat162float(hx), __bfloat162float(hy));  // exact repack
    lo = pbf2(x - __bfloat162float(hx), y - __bfloat162float(hy));
}

// ---------------------------------------------------------------------------
// Split conversion: q/k/v inputs in one launch (grid.y selects source).
// ---------------------------------------------------------------------------
__global__ __launch_bounds__(256) void asplit3_kernel(
    const float* __restrict__ q, const float* __restrict__ k, const float* __restrict__ v)
{
    const int which = blockIdx.y;
    const float* src = (which == 0) ? q : (which == 1) ? k : v;
    uint32_t* ph = (uint32_t*)((which == 0) ? g_aq_hi : (which == 1) ? g_ak_hi : g_av_hi);
    uint32_t* pl = (uint32_t*)((which == 0) ? g_aq_lo : (which == 1) ? g_ak_lo : g_av_lo);
    int i = blockIdx.x * 256 + threadIdx.x;   // float4 index
    float4 val = ((const float4*)src)[i];
    uint32_t h0, l0, h1, l1;
    split2(val.x, val.y, h0, l0);
    split2(val.z, val.w, h1, l1);
    ph[2*i] = h0; ph[2*i+1] = h1;
    pl[2*i] = l0; pl[2*i+1] = l1;
}

// All 4 weights in one launch (grid.z selects).
__global__ __launch_bounds__(256) void wsplit4_kernel(
    const float* __restrict__ Wq, const float* __restrict__ Wk,
    const float* __restrict__ Wv, const float* __restrict__ Wo)
{
    __shared__ float tile[32][33];
    const int z = blockIdx.z;
    const float* W = (z == 0) ? Wq : (z == 1) ? Wk : (z == 2) ? Wv : Wo;
    __nv_bfloat16* dh = (z == 0) ? g_wq_hi : (z == 1) ? g_wk_hi : (z == 2) ? g_wv_hi : g_wo_hi;
    __nv_bfloat16* dl = (z == 0) ? g_wq_lo : (z == 1) ? g_wk_lo : (z == 2) ? g_wv_lo : g_wo_lo;
    const int n0 = blockIdx.x * 32, d0 = blockIdx.y * 32;
    const int tx = threadIdx.x & 31, ty = threadIdx.x >> 5;
    #pragma unroll
    for (int r = ty; r < 32; r += 8)
        tile[r][tx] = W[(size_t)(d0 + r) * 1024 + n0 + tx];
    __syncthreads();
    #pragma unroll
    for (int r = ty; r < 32; r += 8) {
        float v = tile[tx][r];   // = W[d0+tx][n0+r]
        __nv_bfloat16 h = __float2bfloat16(v);
        size_t o = (size_t)(n0 + r) * 1024 + d0 + tx;
        dh[o] = h;
        dl[o] = __float2bfloat16(v - __bfloat162float(h));
    }
}

// ---------------------------------------------------------------------------
// GEMM body (validated round 6/7): BM=128 BN=64 BK=32, static 48KB smem.
// outF != null: fp32 [m][1024]; else split bf16 scatter to [b][h][t][dk].
// ---------------------------------------------------------------------------
__device__ __forceinline__ void gemm_body(
    uint8_t* sm,
    const __nv_bfloat16* __restrict__ Ahp, const __nv_bfloat16* __restrict__ Alp,
    const __nv_bfloat16* __restrict__ Bhp, const __nv_bfloat16* __restrict__ Blp,
    const float* __restrict__ bias, float scale,
    float* __restrict__ outF,
    __nv_bfloat16* __restrict__ outH, __nv_bfloat16* __restrict__ outL)
{
    const uint32_t sb0 = smem_to_u32(sm);
    const int tid = threadIdx.x;
    const int lane = tid & 31, w = tid >> 5;
    const int wm = w >> 1, wn = w & 1;           // 4 x 2 warp grid (32m x 32n each)
    const int n0 = blockIdx.x * 64, m0 = blockIdx.y * 128;
    const int rlo = lane & 15, chf = lane >> 4;

    float acc[2][4][4];
    #pragma unroll
    for (int a = 0; a < 2; a++)
        #pragma unroll
        for (int b = 0; b < 4; b++)
            #pragma unroll
            for (int c = 0; c < 4; c++) acc[a][b][c] = 0.f;

    auto load_stage = [&](int st, int k0) {
        const uint32_t sbase = sb0 + (uint32_t)st * 24576u;
        #pragma unroll
        for (int it = 0; it < 6; it++) {
            int idx = it * 256 + tid;            // 0..1535
            if (idx < 1024) {                    // A: 128 rows x 8 slots
                int row = idx >> 3, c16 = idx & 7;
                const __nv_bfloat16* src = (c16 < 4) ? Ahp : Alp;
                cp16(swz(sbase, row, c16),
                     src + (size_t)(m0 + row) * 1024 + k0 + (c16 & 3) * 8);
            } else {                             // B: 64 rows x 8 slots
                int j = idx - 1024;
                int row = j >> 3, c16 = j & 7;
                const __nv_bfloat16* src = (c16 < 4) ? Bhp : Blp;
                cp16(swz(sbase + 16384u, row, c16),
                     src + (size_t)(n0 + row) * 1024 + k0 + (c16 & 3) * 8);
            }
        }
    };

    load_stage(0, 0);
    cp_commit();

    for (int itk = 0; itk < 32; itk++) {
        __syncthreads();
        if (itk + 1 < 32) { load_stage((itk + 1) & 1, (itk + 1) * 32); cp_commit(); }
        if (itk + 1 < 32) cp_wait<1>(); else cp_wait<0>();
        __syncthreads();

        const uint32_t Ab = sb0 + (uint32_t)(itk & 1) * 24576u;
        const uint32_t Bb = Ab + 16384u;
        #pragma unroll
        for (int ks = 0; ks < 2; ks++) {
            uint32_t ah[2][4], al[2][4];
            #pragma unroll
            for (int mf = 0; mf < 2; mf++) {
                const int arow = wm * 32 + mf * 16 + rlo;
                ldsm4(ah[mf], swz(Ab, arow, ks * 2 + chf));
                ldsm4(al[mf], swz(Ab, arow, ks * 2 + chf + 4));
            }
            #pragma unroll
            for (int h2 = 0; h2 < 2; h2++) {
                uint32_t bh[4], bl[4];
                const int brow = wn * 32 + h2 * 16 + rlo;
                ldsm4(bh, swz(Bb, brow, ks * 2 + chf));
                ldsm4(bl, swz(Bb, brow, ks * 2 + chf + 4));
                #pragma unroll
                for (int i = 0; i < 2; i++) {
                    const int nf = h2 * 2 + i;
                    #pragma unroll
                    for (int mf = 0; mf < 2; mf++) {
                        mma_bf16(acc[mf][nf], ah[mf], bh[i], bh[i + 2]);
                        mma_bf16(acc[mf][nf], ah[mf], bl[i], bl[i + 2]);
                        mma_bf16(acc[mf][nf], al[mf], bh[i], bh[i + 2]);
                    }
                }
            }
        }
    }

    // Epilogue
    const int g = lane >> 2, t4 = lane & 3;
    #pragma unroll
    for (int mf = 0; mf < 2; mf++) {
        #pragma unroll
        for (int nf = 0; nf < 4; nf++) {
            const int m = m0 + wm * 32 + mf * 16 + g;
            const int n = n0 + wn * 32 + nf * 8 + t4 * 2;
            const float b0 = __ldg(&bias[n]), b1 = __ldg(&bias[n + 1]);
            const float v00 = (acc[mf][nf][0] + b0) * scale;
            const float v01 = (acc[mf][nf][1] + b1) * scale;
            const float v10 = (acc[mf][nf][2] + b0) * scale;
            const float v11 = (acc[mf][nf][3] + b1) * scale;
            if (outF) {
                *(float2*)&outF[(size_t)m * 1024 + n]       = make_float2(v00, v01);
                *(float2*)&outF[(size_t)(m + 8) * 1024 + n] = make_float2(v10, v11);
            } else {
                const int bb = m >> 11, tq = m & 2047;
                const int hh = n >> 6, dk = n & 63;
                const size_t o0 = (((size_t)(bb * 16 + hh)) * 2048 + tq) * 64 + dk;
                uint32_t hv, lv;
                split2(v00, v01, hv, lv);
                *(uint32_t*)&outH[o0] = hv; *(uint32_t*)&outL[o0] = lv;
                split2(v10, v11, hv, lv);
                *(uint32_t*)&outH[o0 + 8 * 64] = hv; *(uint32_t*)&outL[o0 + 8 * 64] = lv;
            }
        }
    }
}

// QKV projections in ONE launch: grid.z = 0/1/2 selects q/k/v.
__global__ __launch_bounds__(256) void gemm_qkv_kernel(
    const float* __restrict__ bq, const float* __restrict__ bk, const float* __restrict__ bv)
{
    __shared__ uint8_t sm[49152];
    const int z = blockIdx.z;
    const __nv_bfloat16* Ah = (z == 0) ? g_aq_hi : (z == 1) ? g_ak_hi : g_av_hi;
    const __nv_bfloat16* Al = (z == 0) ? g_aq_lo : (z == 1) ? g_ak_lo : g_av_lo;
    const __nv_bfloat16* Bh = (z == 0) ? g_wq_hi : (z == 1) ? g_wk_hi : g_wv_hi;
    const __nv_bfloat16* Bl = (z == 0) ? g_wq_lo : (z == 1) ? g_wk_lo : g_wv_lo;
    const float* bias = (z == 0) ? bq : (z == 1) ? bk : bv;
    __nv_bfloat16* oh = (z == 0) ? g_qh : (z == 1) ? g_kh : g_vh;
    __nv_bfloat16* ol = (z == 0) ? g_ql : (z == 1) ? g_kl : g_vl;
    gemm_body(sm, Ah, Al, Bh, Bl, bias, (z == 0) ? 0.125f : 1.f, nullptr, oh, ol);
}

// Output projection.
__global__ __launch_bounds__(256) void gemm_out_kernel(
    const float* __restrict__ bo, float* __restrict__ out)
{
    __shared__ uint8_t sm[49152];
    gemm_body(sm, g_ao_hi, g_ao_lo, g_wo_hi, g_wo_lo, bo, 1.f, out, nullptr, nullptr);
}

// ---------------------------------------------------------------------------
// Flash attention via mma.sync bf16 split. BR=128/CTA, BC=64, DK=64.
// 8 warps; warp w owns rows [w*16, w*16+16). Q frags persist in registers.
// STATIC smem 48KB: prologue Q hi@0 lo@16K; then K double-buffer (2x16KB:
// Kh@st*16K, Kl@st*16K+8K) + V single buffer @32K (Vh@32K, Vl@40K).
// Epilogue writes split bf16 directly into g_ao_{hi,lo} [m][1024].
// ---------------------------------------------------------------------------
__global__ __launch_bounds__(256) void flash_mma_kernel()
{
    __shared__ uint8_t sm[49152];
    const uint32_t sb0 = smem_to_u32(sm);
    const int tid = threadIdx.x, lane = tid & 31, w = tid >> 5;
    const int bh = blockIdx.y, t0 = blockIdx.x * 128;
    const size_t qoff = (size_t)bh * (2048 * 64) + (size_t)t0 * 64;
    const size_t kvb = (size_t)bh * (2048 * 64);
    const int rlo = lane & 15, chf = lane >> 4;
    const float L2E = 1.4426950408889634f;

    // ---- Prologue: Q hi/lo to smem, then to register fragments ----
    #pragma unroll
    for (int it = 0; it < 8; it++) {
        int idx = it * 256 + tid;           // 0..2047
        int buf = idx >> 10;                // 0 hi, 1 lo
        int row = (idx & 1023) >> 3, c16 = idx & 7;
        const __nv_bfloat16* src = buf ? g_ql : g_qh;
        cp16(swz(sb0 + (uint32_t)buf * 16384u, row, c16),
             src + qoff + (size_t)row * 64 + c16 * 8);
    }
    cp_commit();
    cp_wait<0>();
    __syncthreads();

    uint32_t qh[4][4], ql[4][4];
    #pragma unroll
    for (int ks = 0; ks < 4; ks++) {
        ldsm4(qh[ks], swz(sb0,           w * 16 + rlo, ks * 2 + chf));
        ldsm4(ql[ks], swz(sb0 + 16384u,  w * 16 + rlo, ks * 2 + chf));
    }
    __syncthreads();   // Q reads done before KV overwrites smem

    auto load_k = [&](int st, int s0) {
        const uint32_t sbase = sb0 + (uint32_t)st * 16384u;
        #pragma unroll
        for (int it = 0; it < 4; it++) {
            int idx = it * 256 + tid;       // 0..1023
            int buf = idx >> 9;             // 0 hi, 1 lo
            int row = (idx & 511) >> 3, c16 = idx & 7;
            const __nv_bfloat16* src = buf ? g_kl : g_kh;
            cp16(swz(sbase + (uint32_t)buf * 8192u, row, c16),
                 src + kvb + (size_t)(s0 + row) * 64 + c16 * 8);
        }
    };
    auto load_v = [&](int s0) {
        const uint32_t sbase = sb0 + 32768u;
        #pragma unroll
        for (int it = 0; it < 4; it++) {
            int idx = it * 256 + tid;       // 0..1023
            int buf = idx >> 9;             // 0 hi, 1 lo
            int row = (idx & 511) >> 3, c16 = idx & 7;
            const __nv_bfloat16* src = buf ? g_vl : g_vh;
            cp16(swz(sbase + (uint32_t)buf * 8192u, row, c16),
                 src + kvb + (size_t)(s0 + row) * 64 + c16 * 8);
        }
    };

    load_k(0, 0);
    cp_commit();                            // group: K(0)

    float O[8][4];
    #pragma unroll
    for (int a = 0; a < 8; a++)
        #pragma unroll
        for (int b = 0; b < 4; b++) O[a][b] = 0.f;
    float m0_ = -1e30f, m1_ = -1e30f, l0_ = 0.f, l1_ = 0.f;

    for (int i = 0; i < 32; i++) {
        const int s0 = i * 64;
        __syncthreads();                    // prev V reads + K[(i+1)&1] reads done
        load_v(s0); cp_commit();            // group V(i)
        if (i + 1 < 32) { load_k((i + 1) & 1, s0 + 64); cp_commit(); }  // group K(i+1)
        // need K(i): pending allowed = V(i) [+ K(i+1)]
        if (i + 1 < 32) cp_wait<2>(); else cp_wait<1>();
        __syncthreads();

        const uint32_t Kb = sb0 + (uint32_t)(i & 1) * 16384u;

        // ---- scores: S[16 x 64] per warp ----
        float sacc[8][4];
        #pragma unroll
        for (int a = 0; a < 8; a++)
            #pragma unroll
            for (int b = 0; b < 4; b++) sacc[a][b] = 0.f;

        #pragma unroll
        for (int ks = 0; ks < 4; ks++) {
            #pragma unroll
            for (int h2 = 0; h2 < 4; h2++) {
                uint32_t kb[4], lb[4];
                ldsm4(kb, swz(Kb,          h2 * 16 + rlo, ks * 2 + chf));
                ldsm4(lb, swz(Kb + 8192u,  h2 * 16 + rlo, ks * 2 + chf));
                #pragma unroll
                for (int ii = 0; ii < 2; ii++) {
                    const int nf = h2 * 2 + ii;
                    mma_bf16(sacc[nf], qh[ks], kb[ii], kb[ii + 2]);
                    mma_bf16(sacc[nf], qh[ks], lb[ii], lb[ii + 2]);
                    mma_bf16(sacc[nf], ql[ks], kb[ii], kb[ii + 2]);
                }
            }
        }

        // ---- online softmax (rows g, g+8 per thread) ----
        float tm0 = -1e30f, tm1 = -1e30f;
        #pragma unroll
        for (int nf = 0; nf < 8; nf++) {
            tm0 = fmaxf(tm0, fmaxf(sacc[nf][0], sacc[nf][1]));
            tm1 = fmaxf(tm1, fmaxf(sacc[nf][2], sacc[nf][3]));
        }
        tm0 = fmaxf(tm0, __shfl_xor_sync(0xffffffffu, tm0, 1));
        tm0 = fmaxf(tm0, __shfl_xor_sync(0xffffffffu, tm0, 2));
        tm1 = fmaxf(tm1, __shfl_xor_sync(0xffffffffu, tm1, 1));
        tm1 = fmaxf(tm1, __shfl_xor_sync(0xffffffffu, tm1, 2));
        float mn0 = fmaxf(m0_, tm0), mn1 = fmaxf(m1_, tm1);
        float c0 = ex2((m0_ - mn0) * L2E), c1 = ex2((m1_ - mn1) * L2E);
        m0_ = mn0; m1_ = mn1;

        uint32_t ph0[8], ph1[8], pl0[8], pl1[8];
        float s0s = 0.f, s1s = 0.f;
        #pragma unroll
        for (int nf = 0; nf < 8; nf++) {
            float p00 = ex2((sacc[nf][0] - mn0) * L2E);
            float p01 = ex2((sacc[nf][1] - mn0) * L2E);
            float p10 = ex2((sacc[nf][2] - mn1) * L2E);
            float p11 = ex2((sacc[nf][3] - mn1) * L2E);
            s0s += p00 + p01; s1s += p10 + p11;
            split2(p00, p01, ph0[nf], pl0[nf]);
            split2(p10, p11, ph1[nf], pl1[nf]);
        }
        s0s += __shfl_xor_sync(0xffffffffu, s0s, 1);
        s0s += __shfl_xor_sync(0xffffffffu, s0s, 2);
        s1s += __shfl_xor_sync(0xffffffffu, s1s, 1);
        s1s += __shfl_xor_sync(0xffffffffu, s1s, 2);
        l0_ = l0_ * c0 + s0s;
        l1_ = l1_ * c1 + s1s;
        #pragma unroll
        for (int nd = 0; nd < 8; nd++) {
            O[nd][0] *= c0; O[nd][1] *= c0;
            O[nd][2] *= c1; O[nd][3] *= c1;
        }

        // ---- wait V(i), then O += P @ V ----
        if (i + 1 < 32) cp_wait<1>(); else cp_wait<0>();
        __syncthreads();

        const uint32_t Vb = sb0 + 32768u;
        #pragma unroll
        for (int ks2 = 0; ks2 < 4; ks2++) {
            uint32_t ah[4] = { ph0[2 * ks2], ph1[2 * ks2], ph0[2 * ks2 + 1], ph1[2 * ks2 + 1] };
            uint32_t al[4] = { pl0[2 * ks2], pl1[2 * ks2], pl0[2 * ks2 + 1], pl1[2 * ks2 + 1] };
            #pragma unroll
            for (int h2 = 0; h2 < 4; h2++) {
                uint32_t vb[4], wb[4];
                ldsm4t(vb, swz(Vb,          ks2 * 16 + rlo, h2 * 2 + chf));
                ldsm4t(wb, swz(Vb + 8192u,  ks2 * 16 + rlo, h2 * 2 + chf));
                #pragma unroll
                for (int ii = 0; ii < 2; ii++) {
                    const int nd = h2 * 2 + ii;
                    mma_bf16(O[nd], ah, vb[2 * ii], vb[2 * ii + 1]);
                    mma_bf16(O[nd], ah, wb[2 * ii], wb[2 * ii + 1]);
                    mma_bf16(O[nd], al, vb[2 * ii], vb[2 * ii + 1]);
                }
            }
        }
    }

    // ---- epilogue: normalize, split, write directly to g_ao_{hi,lo} [m][1024] ----
    const int g = lane >> 2, t4 = lane & 3;
    const int bb = bh >> 4, hh = bh & 15;
    const float inv0 = 1.f / l0_, inv1 = 1.f / l1_;
    const int tq = t0 + w * 16 + g;
    #pragma unroll
    for (int nd = 0; nd < 8; nd++) {
        const int col = nd * 8 + t4 * 2;
        size_t o = ((size_t)(bb * 2048 + tq)) * 1024 + hh * 64 + col;
        uint32_t hv, lv;
        split2(O[nd][0] * inv0, O[nd][1] * inv0, hv, lv);
        *(uint32_t*)&g_ao_hi[o] = hv; *(uint32_t*)&g_ao_lo[o] = lv;
        split2(O[nd][2] * inv1, O[nd][3] * inv1, hv, lv);
        *(uint32_t*)&g_ao_hi[o + 8 * 1024] = hv; *(uint32_t*)&g_ao_lo[o + 8 * 1024] = lv;
    }
}

// ---------------------------------------------------------------------------
extern "C" void kernel_launch(void* const* d_in, const int* in_sizes, int n_in,
                              void* d_out, int out_size)
{
    (void)in_sizes; (void)n_in; (void)out_size;
    const float* query = (const float*)d_in[0];
    const float* value = (const float*)d_in[1];
    const float* key   = (const float*)d_in[2];
    const float* Wq    = (const float*)d_in[3];
    const float* bq    = (const float*)d_in[4];
    const float* Wk    = (const float*)d_in[5];
    const float* bk    = (const float*)d_in[6];
    const float* Wv    = (const float*)d_in[7];
    const float* bv    = (const float*)d_in[8];
    const float* Wo    = (const float*)d_in[9];
    const float* bo    = (const float*)d_in[10];
    float* out = (float*)d_out;

    asplit3_kernel<<<dim3(4096, 3), 256>>>(query, key, value);
    wsplit4_kernel<<<dim3(32, 32, 4), 256>>>(Wq, Wk, Wv, Wo);
    gemm_qkv_kernel<<<dim3(16, 32, 3), 256>>>(bq, bk, bv);
    flash_mma_kernel<<<dim3(T_ / 128, B_ * H_), 256>>>();
    gemm_out_kernel<<<dim3(16, 32), 256>>>(bo, out);
}

// round 10
// speedup vs baseline: 3.7633x; 1.0296x over previous
#include <cuda_runtime.h>
#include <cuda_bf16.h>
#include <cstdint>
#include <math.h>

// Problem dims
#define B_  2
#define T_  2048
#define S_  2048
#define D_  1024
#define H_  16
#define DK_ 64

// ---------------------------------------------------------------------------
// Scratch (device globals; no allocation allowed)
// ---------------------------------------------------------------------------
// GEMM A operands, split hi/lo, [m][k] row-major (m=4096, k=1024)
__device__ __nv_bfloat16 g_aq_hi[4096*1024];
__device__ __nv_bfloat16 g_aq_lo[4096*1024];
__device__ __nv_bfloat16 g_ak_hi[4096*1024];
__device__ __nv_bfloat16 g_ak_lo[4096*1024];
__device__ __nv_bfloat16 g_av_hi[4096*1024];
__device__ __nv_bfloat16 g_av_lo[4096*1024];
__device__ __nv_bfloat16 g_ao_hi[4096*1024];   // attn output (written by flash)
__device__ __nv_bfloat16 g_ao_lo[4096*1024];
// W^T operands, split, [n][k]
__device__ __nv_bfloat16 g_wq_hi[1024*1024];
__device__ __nv_bfloat16 g_wq_lo[1024*1024];
__device__ __nv_bfloat16 g_wk_hi[1024*1024];
__device__ __nv_bfloat16 g_wk_lo[1024*1024];
__device__ __nv_bfloat16 g_wv_hi[1024*1024];
__device__ __nv_bfloat16 g_wv_lo[1024*1024];
__device__ __nv_bfloat16 g_wo_hi[1024*1024];
__device__ __nv_bfloat16 g_wo_lo[1024*1024];
// Projected q/k/v, split hi/lo, [b][h][t][dk]
__device__ __nv_bfloat16 g_qh[B_*H_*T_*DK_];
__device__ __nv_bfloat16 g_ql[B_*H_*T_*DK_];
__device__ __nv_bfloat16 g_kh[B_*H_*S_*DK_];
__device__ __nv_bfloat16 g_kl[B_*H_*S_*DK_];
__device__ __nv_bfloat16 g_vh[B_*H_*S_*DK_];
__device__ __nv_bfloat16 g_vl[B_*H_*S_*DK_];

// ---------------------------------------------------------------------------
// Helpers (base-sm_103-safe: mma.sync / ldmatrix / cp.async only)
// ---------------------------------------------------------------------------
__device__ __forceinline__ uint32_t smem_to_u32(const void* p) {
    uint32_t a;
    asm("{ .reg .u64 t; cvta.to.shared.u64 t, %1; cvt.u32.u64 %0, t; }" : "=r"(a) : "l"(p));
    return a;
}
__device__ __forceinline__ void cp16(uint32_t d, const void* s) {
    asm volatile("cp.async.cg.shared.global [%0], [%1], 16;" :: "r"(d), "l"(s));
}
__device__ __forceinline__ void cp_commit() { asm volatile("cp.async.commit_group;" ::: "memory"); }
template<int N> __device__ __forceinline__ void cp_wait() {
    asm volatile("cp.async.wait_group %0;" :: "n"(N) : "memory");
}
__device__ __forceinline__ void ldsm4(uint32_t* r, uint32_t a) {
    asm volatile("ldmatrix.sync.aligned.m8n8.x4.shared.b16 {%0,%1,%2,%3}, [%4];"
                 : "=r"(r[0]), "=r"(r[1]), "=r"(r[2]), "=r"(r[3]) : "r"(a));
}
__device__ __forceinline__ void ldsm4t(uint32_t* r, uint32_t a) {
    asm volatile("ldmatrix.sync.aligned.m8n8.x4.trans.shared.b16 {%0,%1,%2,%3}, [%4];"
                 : "=r"(r[0]), "=r"(r[1]), "=r"(r[2]), "=r"(r[3]) : "r"(a));
}
__device__ __forceinline__ void mma_bf16(float* c, const uint32_t* a, uint32_t b0, uint32_t b1) {
    asm volatile(
        "mma.sync.aligned.m16n8k16.row.col.f32.bf16.bf16.f32 "
        "{%0,%1,%2,%3}, {%4,%5,%6,%7}, {%8,%9}, {%0,%1,%2,%3};"
        : "+f"(c[0]), "+f"(c[1]), "+f"(c[2]), "+f"(c[3])
        : "r"(a[0]), "r"(a[1]), "r"(a[2]), "r"(a[3]), "r"(b0), "r"(b1));
}
__device__ __forceinline__ float ex2(float x) {
    float y;
    asm("ex2.approx.f32 %0, %1;" : "=f"(y) : "f"(x));
    return y;
}
// 128B-row smem, 16B-column XOR swizzle (conflict-free for ldmatrix)
__device__ __forceinline__ uint32_t swz(uint32_t base, int row, int c16) {
    return base + (uint32_t)row * 128u + (((uint32_t)(c16 ^ (row & 7))) << 4);
}
__device__ __forceinline__ uint32_t pbf2(float x, float y) {
    __nv_bfloat162 t = __floats2bfloat162_rn(x, y);
    return *reinterpret_cast<uint32_t*>(&t);
}
__device__ __forceinline__ void split2(float x, float y, uint32_t& hi, uint32_t& lo) {
    __nv_bfloat16 hx = __float2bfloat16(x), hy = __float2bfloat16(y);
    hi = pbf2(__bfloat162float(hx), __bfloat162float(hy));  // exact repack
    lo = pbf2(x - __bfloat162float(hx), y - __bfloat162float(hy));
}

// ---------------------------------------------------------------------------
// Split conversion: q/k/v inputs in one launch (grid.y selects source).
// ---------------------------------------------------------------------------
__global__ __launch_bounds__(256) void asplit3_kernel(
    const float* __restrict__ q, const float* __restrict__ k, const float* __restrict__ v)
{
    const int which = blockIdx.y;
    const float* src = (which == 0) ? q : (which == 1) ? k : v;
    uint32_t* ph = (uint32_t*)((which == 0) ? g_aq_hi : (which == 1) ? g_ak_hi : g_av_hi);
    uint32_t* pl = (uint32_t*)((which == 0) ? g_aq_lo : (which == 1) ? g_ak_lo : g_av_lo);
    int i = blockIdx.x * 256 + threadIdx.x;   // float4 index
    float4 val = ((const float4*)src)[i];
    uint32_t h0, l0, h1, l1;
    split2(val.x, val.y, h0, l0);
    split2(val.z, val.w, h1, l1);
    ph[2*i] = h0; ph[2*i+1] = h1;
    pl[2*i] = l0; pl[2*i+1] = l1;
}

// All 4 weights in one launch (grid.z selects).
__global__ __launch_bounds__(256) void wsplit4_kernel(
    const float* __restrict__ Wq, const float* __restrict__ Wk,
    const float* __restrict__ Wv, const float* __restrict__ Wo)
{
    __shared__ float tile[32][33];
    const int z = blockIdx.z;
    const float* W = (z == 0) ? Wq : (z == 1) ? Wk : (z == 2) ? Wv : Wo;
    __nv_bfloat16* dh = (z == 0) ? g_wq_hi : (z == 1) ? g_wk_hi : (z == 2) ? g_wv_hi : g_wo_hi;
    __nv_bfloat16* dl = (z == 0) ? g_wq_lo : (z == 1) ? g_wk_lo : (z == 2) ? g_wv_lo : g_wo_lo;
    const int n0 = blockIdx.x * 32, d0 = blockIdx.y * 32;
    const int tx = threadIdx.x & 31, ty = threadIdx.x >> 5;
    #pragma unroll
    for (int r = ty; r < 32; r += 8)
        tile[r][tx] = W[(size_t)(d0 + r) * 1024 + n0 + tx];
    __syncthreads();
    #pragma unroll
    for (int r = ty; r < 32; r += 8) {
        float v = tile[tx][r];   // = W[d0+tx][n0+r]
        __nv_bfloat16 h = __float2bfloat16(v);
        size_t o = (size_t)(n0 + r) * 1024 + d0 + tx;
        dh[o] = h;
        dl[o] = __float2bfloat16(v - __bfloat162float(h));
    }
}

// ---------------------------------------------------------------------------
// GEMM body (validated round 6/7): BM=128 BN=64 BK=32, static 48KB smem.
// outF != null: fp32 [m][1024]; else split bf16 scatter to [b][h][t][dk].
// ---------------------------------------------------------------------------
__device__ __forceinline__ void gemm_body(
    uint8_t* sm,
    const __nv_bfloat16* __restrict__ Ahp, const __nv_bfloat16* __restrict__ Alp,
    const __nv_bfloat16* __restrict__ Bhp, const __nv_bfloat16* __restrict__ Blp,
    const float* __restrict__ bias, float scale,
    float* __restrict__ outF,
    __nv_bfloat16* __restrict__ outH, __nv_bfloat16* __restrict__ outL)
{
    const uint32_t sb0 = smem_to_u32(sm);
    const int tid = threadIdx.x;
    const int lane = tid & 31, w = tid >> 5;
    const int wm = w >> 1, wn = w & 1;           // 4 x 2 warp grid (32m x 32n each)
    const int n0 = blockIdx.x * 64, m0 = blockIdx.y * 128;
    const int rlo = lane & 15, chf = lane >> 4;

    float acc[2][4][4];
    #pragma unroll
    for (int a = 0; a < 2; a++)
        #pragma unroll
        for (int b = 0; b < 4; b++)
            #pragma unroll
            for (int c = 0; c < 4; c++) acc[a][b][c] = 0.f;

    auto load_stage = [&](int st, int k0) {
        const uint32_t sbase = sb0 + (uint32_t)st * 24576u;
        #pragma unroll
        for (int it = 0; it < 6; it++) {
            int idx = it * 256 + tid;            // 0..1535
            if (idx < 1024) {                    // A: 128 rows x 8 slots
                int row = idx >> 3, c16 = idx & 7;
                const __nv_bfloat16* src = (c16 < 4) ? Ahp : Alp;
                cp16(swz(sbase, row, c16),
                     src + (size_t)(m0 + row) * 1024 + k0 + (c16 & 3) * 8);
            } else {                             // B: 64 rows x 8 slots
                int j = idx - 1024;
                int row = j >> 3, c16 = j & 7;
                const __nv_bfloat16* src = (c16 < 4) ? Bhp : Blp;
                cp16(swz(sbase + 16384u, row, c16),
                     src + (size_t)(n0 + row) * 1024 + k0 + (c16 & 3) * 8);
            }
        }
    };

    load_stage(0, 0);
    cp_commit();

    for (int itk = 0; itk < 32; itk++) {
        __syncthreads();
        if (itk + 1 < 32) { load_stage((itk + 1) & 1, (itk + 1) * 32); cp_commit(); }
        if (itk + 1 < 32) cp_wait<1>(); else cp_wait<0>();
        __syncthreads();

        const uint32_t Ab = sb0 + (uint32_t)(itk & 1) * 24576u;
        const uint32_t Bb = Ab + 16384u;
        #pragma unroll
        for (int ks = 0; ks < 2; ks++) {
            uint32_t ah[2][4], al[2][4];
            #pragma unroll
            for (int mf = 0; mf < 2; mf++) {
                const int arow = wm * 32 + mf * 16 + rlo;
                ldsm4(ah[mf], swz(Ab, arow, ks * 2 + chf));
                ldsm4(al[mf], swz(Ab, arow, ks * 2 + chf + 4));
            }
            #pragma unroll
            for (int h2 = 0; h2 < 2; h2++) {
                uint32_t bh[4], bl[4];
                const int brow = wn * 32 + h2 * 16 + rlo;
                ldsm4(bh, swz(Bb, brow, ks * 2 + chf));
                ldsm4(bl, swz(Bb, brow, ks * 2 + chf + 4));
                #pragma unroll
                for (int i = 0; i < 2; i++) {
                    const int nf = h2 * 2 + i;
                    #pragma unroll
                    for (int mf = 0; mf < 2; mf++) {
                        mma_bf16(acc[mf][nf], ah[mf], bh[i], bh[i + 2]);
                        mma_bf16(acc[mf][nf], ah[mf], bl[i], bl[i + 2]);
                        mma_bf16(acc[mf][nf], al[mf], bh[i], bh[i + 2]);
                    }
                }
            }
        }
    }

    // Epilogue
    const int g = lane >> 2, t4 = lane & 3;
    #pragma unroll
    for (int mf = 0; mf < 2; mf++) {
        #pragma unroll
        for (int nf = 0; nf < 4; nf++) {
            const int m = m0 + wm * 32 + mf * 16 + g;
            const int n = n0 + wn * 32 + nf * 8 + t4 * 2;
            const float b0 = __ldg(&bias[n]), b1 = __ldg(&bias[n + 1]);
            const float v00 = (acc[mf][nf][0] + b0) * scale;
            const float v01 = (acc[mf][nf][1] + b1) * scale;
            const float v10 = (acc[mf][nf][2] + b0) * scale;
            const float v11 = (acc[mf][nf][3] + b1) * scale;
            if (outF) {
                *(float2*)&outF[(size_t)m * 1024 + n]       = make_float2(v00, v01);
                *(float2*)&outF[(size_t)(m + 8) * 1024 + n] = make_float2(v10, v11);
            } else {
                const int bb = m >> 11, tq = m & 2047;
                const int hh = n >> 6, dk = n & 63;
                const size_t o0 = (((size_t)(bb * 16 + hh)) * 2048 + tq) * 64 + dk;
                uint32_t hv, lv;
                split2(v00, v01, hv, lv);
                *(uint32_t*)&outH[o0] = hv; *(uint32_t*)&outL[o0] = lv;
                split2(v10, v11, hv, lv);
                *(uint32_t*)&outH[o0 + 8 * 64] = hv; *(uint32_t*)&outL[o0 + 8 * 64] = lv;
            }
        }
    }
}

// QKV projections in ONE launch: grid.z = 0/1/2 selects q/k/v.
__global__ __launch_bounds__(256) void gemm_qkv_kernel(
    const float* __restrict__ bq, const float* __restrict__ bk, const float* __restrict__ bv)
{
    __shared__ uint8_t sm[49152];
    const int z = blockIdx.z;
    const __nv_bfloat16* Ah = (z == 0) ? g_aq_hi : (z == 1) ? g_ak_hi : g_av_hi;
    const __nv_bfloat16* Al = (z == 0) ? g_aq_lo : (z == 1) ? g_ak_lo : g_av_lo;
    const __nv_bfloat16* Bh = (z == 0) ? g_wq_hi : (z == 1) ? g_wk_hi : g_wv_hi;
    const __nv_bfloat16* Bl = (z == 0) ? g_wq_lo : (z == 1) ? g_wk_lo : g_wv_lo;
    const float* bias = (z == 0) ? bq : (z == 1) ? bk : bv;
    __nv_bfloat16* oh = (z == 0) ? g_qh : (z == 1) ? g_kh : g_vh;
    __nv_bfloat16* ol = (z == 0) ? g_ql : (z == 1) ? g_kl : g_vl;
    gemm_body(sm, Ah, Al, Bh, Bl, bias, (z == 0) ? 0.125f : 1.f, nullptr, oh, ol);
}

// Output projection.
__global__ __launch_bounds__(256) void gemm_out_kernel(
    const float* __restrict__ bo, float* __restrict__ out)
{
    __shared__ uint8_t sm[49152];
    gemm_body(sm, g_ao_hi, g_ao_lo, g_wo_hi, g_wo_lo, bo, 1.f, out, nullptr, nullptr);
}

// ---------------------------------------------------------------------------
// Flash attention via mma.sync bf16 split. BR=128/CTA, K tile 64 cols,
// processed as TWO 32-col halves to cap register pressure (2 CTAs/SM).
// 8 warps; warp w owns rows [w*16, w*16+16). Q frags persist in registers.
// STATIC smem 48KB: prologue Q hi@0 lo@16K; then K double-buffer (2x16KB)
// + V single buffer @32K. Epilogue: split bf16 direct to g_ao_{hi,lo}.
// ---------------------------------------------------------------------------
__global__ __launch_bounds__(256, 2) void flash_mma_kernel()
{
    __shared__ uint8_t sm[49152];
    const uint32_t sb0 = smem_to_u32(sm);
    const int tid = threadIdx.x, lane = tid & 31, w = tid >> 5;
    const int bh = blockIdx.y, t0 = blockIdx.x * 128;
    const size_t qoff = (size_t)bh * (2048 * 64) + (size_t)t0 * 64;
    const size_t kvb = (size_t)bh * (2048 * 64);
    const int rlo = lane & 15, chf = lane >> 4;
    const float L2E = 1.4426950408889634f;

    // ---- Prologue: Q hi/lo to smem, then to register fragments ----
    #pragma unroll
    for (int it = 0; it < 8; it++) {
        int idx = it * 256 + tid;           // 0..2047
        int buf = idx >> 10;                // 0 hi, 1 lo
        int row = (idx & 1023) >> 3, c16 = idx & 7;
        const __nv_bfloat16* src = buf ? g_ql : g_qh;
        cp16(swz(sb0 + (uint32_t)buf * 16384u, row, c16),
             src + qoff + (size_t)row * 64 + c16 * 8);
    }
    cp_commit();
    cp_wait<0>();
    __syncthreads();

    uint32_t qh[4][4], ql[4][4];
    #pragma unroll
    for (int ks = 0; ks < 4; ks++) {
        ldsm4(qh[ks], swz(sb0,           w * 16 + rlo, ks * 2 + chf));
        ldsm4(ql[ks], swz(sb0 + 16384u,  w * 16 + rlo, ks * 2 + chf));
    }
    __syncthreads();   // Q reads done before KV overwrites smem

    auto load_k = [&](int st, int s0) {
        const uint32_t sbase = sb0 + (uint32_t)st * 16384u;
        #pragma unroll
        for (int it = 0; it < 4; it++) {
            int idx = it * 256 + tid;       // 0..1023
            int buf = idx >> 9;             // 0 hi, 1 lo
            int row = (idx & 511) >> 3, c16 = idx & 7;
            const __nv_bfloat16* src = buf ? g_kl : g_kh;
            cp16(swz(sbase + (uint32_t)buf * 8192u, row, c16),
                 src + kvb + (size_t)(s0 + row) * 64 + c16 * 8);
        }
    };
    auto load_v = [&](int s0) {
        const uint32_t sbase = sb0 + 32768u;
        #pragma unroll
        for (int it = 0; it < 4; it++) {
            int idx = it * 256 + tid;       // 0..1023
            int buf = idx >> 9;             // 0 hi, 1 lo
            int row = (idx & 511) >> 3, c16 = idx & 7;
            const __nv_bfloat16* src = buf ? g_vl : g_vh;
            cp16(swz(sbase + (uint32_t)buf * 8192u, row, c16),
                 src + kvb + (size_t)(s0 + row) * 64 + c16 * 8);
        }
    };

    load_k(0, 0);
    cp_commit();                            // group: K(0)

    float O[8][4];
    #pragma unroll
    for (int a = 0; a < 8; a++)
        #pragma unroll
        for (int b = 0; b < 4; b++) O[a][b] = 0.f;
    float m0_ = -1e30f, m1_ = -1e30f, l0_ = 0.f, l1_ = 0.f;

    for (int i = 0; i < 32; i++) {
        const int s0 = i * 64;
        __syncthreads();                    // prev V reads + K[(i+1)&1] reads done
        load_v(s0); cp_commit();            // group V(i)
        if (i + 1 < 32) { load_k((i + 1) & 1, s0 + 64); cp_commit(); }  // group K(i+1)
        // need K(i): pending allowed = V(i) [+ K(i+1)]
        if (i + 1 < 32) cp_wait<2>(); else cp_wait<1>();
        __syncthreads();

        const uint32_t Kb = sb0 + (uint32_t)(i & 1) * 16384u;
        const uint32_t Vb = sb0 + 32768u;

        #pragma unroll
        for (int half = 0; half < 2; half++) {
            // ---- scores: S[16 x 32] per warp (columns half*32..half*32+31) ----
            float sacc[4][4];
            #pragma unroll
            for (int a = 0; a < 4; a++)
                #pragma unroll
                for (int b = 0; b < 4; b++) sacc[a][b] = 0.f;

            #pragma unroll
            for (int ks = 0; ks < 4; ks++) {
                #pragma unroll
                for (int h2l = 0; h2l < 2; h2l++) {
                    const int h2 = half * 2 + h2l;
                    uint32_t kb[4], lb[4];
                    ldsm4(kb, swz(Kb,          h2 * 16 + rlo, ks * 2 + chf));
                    ldsm4(lb, swz(Kb + 8192u,  h2 * 16 + rlo, ks * 2 + chf));
                    #pragma unroll
                    for (int ii = 0; ii < 2; ii++) {
                        const int nf = h2l * 2 + ii;
                        mma_bf16(sacc[nf], qh[ks], kb[ii], kb[ii + 2]);
                        mma_bf16(sacc[nf], qh[ks], lb[ii], lb[ii + 2]);
                        mma_bf16(sacc[nf], ql[ks], kb[ii], kb[ii + 2]);
                    }
                }
            }

            // ---- online softmax (rows g, g+8 per thread) ----
            float tm0 = -1e30f, tm1 = -1e30f;
            #pragma unroll
            for (int nf = 0; nf < 4; nf++) {
                tm0 = fmaxf(tm0, fmaxf(sacc[nf][0], sacc[nf][1]));
                tm1 = fmaxf(tm1, fmaxf(sacc[nf][2], sacc[nf][3]));
            }
            tm0 = fmaxf(tm0, __shfl_xor_sync(0xffffffffu, tm0, 1));
            tm0 = fmaxf(tm0, __shfl_xor_sync(0xffffffffu, tm0, 2));
            tm1 = fmaxf(tm1, __shfl_xor_sync(0xffffffffu, tm1, 1));
            tm1 = fmaxf(tm1, __shfl_xor_sync(0xffffffffu, tm1, 2));
            float mn0 = fmaxf(m0_, tm0), mn1 = fmaxf(m1_, tm1);
            float c0 = ex2((m0_ - mn0) * L2E), c1 = ex2((m1_ - mn1) * L2E);
            m0_ = mn0; m1_ = mn1;

            uint32_t ph0[4], ph1[4], pl0[4], pl1[4];
            float s0s = 0.f, s1s = 0.f;
            #pragma unroll
            for (int nf = 0; nf < 4; nf++) {
                float p00 = ex2((sacc[nf][0] - mn0) * L2E);
                float p01 = ex2((sacc[nf][1] - mn0) * L2E);
                float p10 = ex2((sacc[nf][2] - mn1) * L2E);
                float p11 = ex2((sacc[nf][3] - mn1) * L2E);
                s0s += p00 + p01; s1s += p10 + p11;
                split2(p00, p01, ph0[nf], pl0[nf]);
                split2(p10, p11, ph1[nf], pl1[nf]);
            }
            s0s += __shfl_xor_sync(0xffffffffu, s0s, 1);
            s0s += __shfl_xor_sync(0xffffffffu, s0s, 2);
            s1s += __shfl_xor_sync(0xffffffffu, s1s, 1);
            s1s += __shfl_xor_sync(0xffffffffu, s1s, 2);
            l0_ = l0_ * c0 + s0s;
            l1_ = l1_ * c1 + s1s;
            #pragma unroll
            for (int nd = 0; nd < 8; nd++) {
                O[nd][0] *= c0; O[nd][1] *= c0;
                O[nd][2] *= c1; O[nd][3] *= c1;
            }

            // ---- before first PV of this tile: wait V(i) visible ----
            if (half == 0) {
                if (i + 1 < 32) cp_wait<1>(); else cp_wait<0>();
                __syncthreads();
            }

            // ---- O += P @ V (V rows half*32..half*32+31) ----
            #pragma unroll
            for (int k2l = 0; k2l < 2; k2l++) {
                const int ks2 = half * 2 + k2l;
                uint32_t ah[4] = { ph0[2 * k2l], ph1[2 * k2l], ph0[2 * k2l + 1], ph1[2 * k2l + 1] };
                uint32_t al[4] = { pl0[2 * k2l], pl1[2 * k2l], pl0[2 * k2l + 1], pl1[2 * k2l + 1] };
                #pragma unroll
                for (int h2 = 0; h2 < 4; h2++) {
                    uint32_t vb[4], wb[4];
                    ldsm4t(vb, swz(Vb,          ks2 * 16 + rlo, h2 * 2 + chf));
                    ldsm4t(wb, swz(Vb + 8192u,  ks2 * 16 + rlo, h2 * 2 + chf));
                    #pragma unroll
                    for (int ii = 0; ii < 2; ii++) {
                        const int nd = h2 * 2 + ii;
                        mma_bf16(O[nd], ah, vb[2 * ii], vb[2 * ii + 1]);
                        mma_bf16(O[nd], ah, wb[2 * ii], wb[2 * ii + 1]);
                        mma_bf16(O[nd], al, vb[2 * ii], vb[2 * ii + 1]);
                    }
                }
            }
        }
    }

    // ---- epilogue: normalize, split, write directly to g_ao_{hi,lo} [m][1024] ----
    const int g = lane >> 2, t4 = lane & 3;
    const int bb = bh >> 4, hh = bh & 15;
    const float inv0 = 1.f / l0_, inv1 = 1.f / l1_;
    const int tq = t0 + w * 16 + g;
    #pragma unroll
    for (int nd = 0; nd < 8; nd++) {
        const int col = nd * 8 + t4 * 2;
        size_t o = ((size_t)(bb * 2048 + tq)) * 1024 + hh * 64 + col;
        uint32_t hv, lv;
        split2(O[nd][0] * inv0, O[nd][1] * inv0, hv, lv);
        *(uint32_t*)&g_ao_hi[o] = hv; *(uint32_t*)&g_ao_lo[o] = lv;
        split2(O[nd][2] * inv1, O[nd][3] * inv1, hv, lv);
        *(uint32_t*)&g_ao_hi[o + 8 * 1024] = hv; *(uint32_t*)&g_ao_lo[o + 8 * 1024] = lv;
    }
}

// ---------------------------------------------------------------------------
extern "C" void kernel_launch(void* const* d_in, const int* in_sizes, int n_in,
                              void* d_out, int out_size)
{
    (void)in_sizes; (void)n_in; (void)out_size;
    const float* query = (const float*)d_in[0];
    const float* value = (const float*)d_in[1];
    const float* key   = (const float*)d_in[2];
    const float* Wq    = (const float*)d_in[3];
    const float* bq    = (const float*)d_in[4];
    const float* Wk    = (const float*)d_in[5];
    const float* bk    = (const float*)d_in[6];
    const float* Wv    = (const float*)d_in[7];
    const float* bv    = (const float*)d_in[8];
    const float* Wo    = (const float*)d_in[9];
    const float* bo    = (const float*)d_in[10];
    float* out = (float*)d_out;

    asplit3_kernel<<<dim3(4096, 3), 256>>>(query, key, value);
    wsplit4_kernel<<<dim3(32, 32, 4), 256>>>(Wq, Wk, Wv, Wo);
    gemm_qkv_kernel<<<dim3(16, 32, 3), 256>>>(bq, bk, bv);
    flash_mma_kernel<<<dim3(T_ / 128, B_ * H_), 256>>>();
    gemm_out_kernel<<<dim3(16, 32), 256>>>(bo, out);
}